// round 1
// baseline (speedup 1.0000x reference)
#include <cuda_runtime.h>
#include <math.h>

#define BATCHN 65536
#define NROWS  (BATCHN * 8)    // 524288 neighbor rows
#define HIDD   128
#define OBSD   114
#define NGRP   8192            // BATCH / NUM_AGENTS

// ---- scratch (static device globals; no runtime allocation) ----
__device__ float g_e [(size_t)NROWS  * HIDD];   // neighbor embeddings  (256 MB)
__device__ float g_v [(size_t)NROWS  * HIDD];   // neighbor values      (256 MB)
__device__ float g_av[(size_t)BATCHN * HIDD];   // agent values         ( 32 MB)

// ============================================================================
// Fused 2-layer tanh MLP:  Y = tanh(tanh(X@W1 + b1) @ W2 + b2)
// Block: 256 threads, processes 64-row tiles. Weights cached in dynamic smem.
// Thread tile: 8 rows x 4 cols -> 32 fp32 accumulators, ~89% FFMA density.
// GATHER mode builds the embed-MLP input directly from obs:
//   row r: cols [0,18)  = obs[r % 65536][0:18]
//          cols [18,30) = obs[r/8][18 + (r%8)*12 : +12]
// K1P is the padded K of layer 1 (32 for embed, 128 otherwise).
// ============================================================================
template<int K1P, bool GATHER>
__global__ void __launch_bounds__(256, 1)
mlp2_kernel(const float* __restrict__ X,
            const float* __restrict__ W1,
            const float* __restrict__ b1,
            const float* __restrict__ W2,
            const float* __restrict__ b2,
            float* __restrict__ Y,
            int K1, int nTiles)
{
    extern __shared__ float sm[];
    float* W1s = sm;                          // K1P * 128
    float* W2s = W1s + K1P * 128;             // 128 * 128
    float* Xs  = W2s + 128 * 128;             // 64 * (K1P + 4)
    float* Hs  = Xs  + 64 * (K1P + 4);        // 64 * 132

    const int tid     = threadIdx.x;
    const int tc      = tid & 31;             // col group (32 groups of 4 cols)
    const int tr      = tid >> 5;             // row group (8 groups of 8 rows)
    const int colBase = tc << 2;
    const int XSS     = K1P + 4;

    // Load weights once per block (amortized over tile loop)
    for (int i = tid; i < K1P * 128; i += 256)
        W1s[i] = (i < K1 * 128) ? W1[i] : 0.0f;
    for (int i = tid; i < 128 * 128; i += 256)
        W2s[i] = W2[i];

    const float4 b1v = *(const float4*)(b1 + colBase);
    const float4 b2v = *(const float4*)(b2 + colBase);

    for (int tile = blockIdx.x; tile < nTiles; tile += gridDim.x) {
        const int row0 = tile * 64;

        // ---- load / gather X tile into smem ----
        if (GATHER) {
            for (int idx = tid; idx < 64 * K1P; idx += 256) {
                int r = idx >> 5;             // K1P == 32
                int k = idx & 31;
                int R = row0 + r;
                float val = 0.0f;
                if (k < 18)
                    val = X[(R & (BATCHN - 1)) * OBSD + k];
                else if (k < 30)
                    val = X[(R >> 3) * OBSD + 18 + (R & 7) * 12 + (k - 18)];
                Xs[r * XSS + k] = val;
            }
        } else {
            for (int idx = tid; idx < 64 * 128; idx += 256) {
                int r = idx >> 7;             // K1P == 128
                int k = idx & 127;
                Xs[r * XSS + k] = X[(size_t)(row0 + r) * 128 + k];
            }
        }
        __syncthreads();

        // ---- layer 1: H = tanh(X @ W1 + b1) ----
        {
            float acc[8][4];
            #pragma unroll
            for (int r = 0; r < 8; r++)
                acc[r][0] = acc[r][1] = acc[r][2] = acc[r][3] = 0.0f;

            for (int k = 0; k < K1P; k += 4) {
                float4 xv[8];
                #pragma unroll
                for (int r = 0; r < 8; r++)
                    xv[r] = *(const float4*)&Xs[(tr * 8 + r) * XSS + k];
                #pragma unroll
                for (int kk = 0; kk < 4; kk++) {
                    float4 w = *(const float4*)&W1s[(k + kk) * 128 + colBase];
                    #pragma unroll
                    for (int r = 0; r < 8; r++) {
                        float xs = (kk == 0) ? xv[r].x : (kk == 1) ? xv[r].y
                                 : (kk == 2) ? xv[r].z : xv[r].w;
                        acc[r][0] = fmaf(xs, w.x, acc[r][0]);
                        acc[r][1] = fmaf(xs, w.y, acc[r][1]);
                        acc[r][2] = fmaf(xs, w.z, acc[r][2]);
                        acc[r][3] = fmaf(xs, w.w, acc[r][3]);
                    }
                }
            }
            #pragma unroll
            for (int r = 0; r < 8; r++) {
                float4 hv;
                hv.x = tanhf(acc[r][0] + b1v.x);
                hv.y = tanhf(acc[r][1] + b1v.y);
                hv.z = tanhf(acc[r][2] + b1v.z);
                hv.w = tanhf(acc[r][3] + b1v.w);
                *(float4*)&Hs[(tr * 8 + r) * 132 + colBase] = hv;
            }
        }
        __syncthreads();

        // ---- layer 2: Y = tanh(H @ W2 + b2) ----
        {
            float acc[8][4];
            #pragma unroll
            for (int r = 0; r < 8; r++)
                acc[r][0] = acc[r][1] = acc[r][2] = acc[r][3] = 0.0f;

            for (int k = 0; k < 128; k += 4) {
                float4 xv[8];
                #pragma unroll
                for (int r = 0; r < 8; r++)
                    xv[r] = *(const float4*)&Hs[(tr * 8 + r) * 132 + k];
                #pragma unroll
                for (int kk = 0; kk < 4; kk++) {
                    float4 w = *(const float4*)&W2s[(k + kk) * 128 + colBase];
                    #pragma unroll
                    for (int r = 0; r < 8; r++) {
                        float xs = (kk == 0) ? xv[r].x : (kk == 1) ? xv[r].y
                                 : (kk == 2) ? xv[r].z : xv[r].w;
                        acc[r][0] = fmaf(xs, w.x, acc[r][0]);
                        acc[r][1] = fmaf(xs, w.y, acc[r][1]);
                        acc[r][2] = fmaf(xs, w.z, acc[r][2]);
                        acc[r][3] = fmaf(xs, w.w, acc[r][3]);
                    }
                }
            }
            #pragma unroll
            for (int r = 0; r < 8; r++) {
                float4 ov;
                ov.x = tanhf(acc[r][0] + b2v.x);
                ov.y = tanhf(acc[r][1] + b2v.y);
                ov.z = tanhf(acc[r][2] + b2v.z);
                ov.w = tanhf(acc[r][3] + b2v.w);
                *(float4*)&Y[(size_t)(row0 + tr * 8 + r) * 128 + colBase] = ov;
            }
        }
        __syncthreads();
    }
}

// ============================================================================
// Per-batch attention over 8 neighbors:
//   q = mean_n(e) / sqrt(128);  s[n] = q . e[n];  attn = softmax(s)
//   AA[b] = sum_n attn[n] * v[n]
// One 128-thread block per batch element.
// ============================================================================
__global__ void __launch_bounds__(128)
attn1_kernel(const float* __restrict__ e,
             const float* __restrict__ v,
             float* __restrict__ AA)
{
    __shared__ float es[8][128];
    __shared__ float vs[8][128];
    __shared__ float qs[128];
    __shared__ float sc[8];

    const int b = blockIdx.x;
    const int j = threadIdx.x;
    const size_t base = (size_t)b * 8 * 128;

    #pragma unroll
    for (int n = 0; n < 8; n++) {
        es[n][j] = e[base + n * 128 + j];
        vs[n][j] = v[base + n * 128 + j];
    }
    __syncthreads();

    float q = 0.0f;
    #pragma unroll
    for (int n = 0; n < 8; n++) q += es[n][j];
    q *= 0.011048543456039806f;               // 1 / (8 * sqrt(128))
    qs[j] = q;
    __syncthreads();

    const int warp = j >> 5, lane = j & 31;
    #pragma unroll
    for (int nn = 0; nn < 2; nn++) {
        int n = warp * 2 + nn;
        float p = 0.0f;
        #pragma unroll
        for (int m = 0; m < 4; m++) {
            int jj = lane + m * 32;
            p += qs[jj] * es[n][jj];
        }
        #pragma unroll
        for (int o = 16; o >= 1; o >>= 1)
            p += __shfl_xor_sync(0xffffffff, p, o);
        if (lane == 0) sc[n] = p;
    }
    __syncthreads();

    float mx = sc[0];
    #pragma unroll
    for (int n = 1; n < 8; n++) mx = fmaxf(mx, sc[n]);
    float wgt[8], wsum = 0.0f;
    #pragma unroll
    for (int n = 0; n < 8; n++) { wgt[n] = expf(sc[n] - mx); wsum += wgt[n]; }
    const float inv = 1.0f / wsum;

    float out = 0.0f;
    #pragma unroll
    for (int n = 0; n < 8; n++) out += wgt[n] * vs[n][j];
    AA[(size_t)b * 128 + j] = out * inv;
}

// ============================================================================
// Per-group multi-head attention (8 heads x 16 dims over 8 agents) + tile x8.
// One 128-thread block per group; thread j = head (j/16), dim (j%16).
// ============================================================================
__global__ void __launch_bounds__(128)
mha_kernel(const float* __restrict__ AA,
           const float* __restrict__ AV,
           float* __restrict__ out)
{
    __shared__ float ks[8][128];
    __shared__ float vs[8][128];

    const int g = blockIdx.x;
    const int j = threadIdx.x;
    const size_t base = (size_t)g * 8 * 128;

    #pragma unroll
    for (int a = 0; a < 8; a++) {
        ks[a][j] = AA[base + a * 128 + j];
        vs[a][j] = AV[base + a * 128 + j];
    }
    __syncthreads();

    float q = 0.0f;
    #pragma unroll
    for (int a = 0; a < 8; a++) q += ks[a][j];
    q *= 0.03125f;                            // (1/8 mean) * (1/sqrt(16))

    float s[8];
    #pragma unroll
    for (int a = 0; a < 8; a++) {
        float p = q * ks[a][j];
        p += __shfl_xor_sync(0xffffffff, p, 8);
        p += __shfl_xor_sync(0xffffffff, p, 4);
        p += __shfl_xor_sync(0xffffffff, p, 2);
        p += __shfl_xor_sync(0xffffffff, p, 1);
        s[a] = p;                             // full 16-dim head dot product
    }

    float mx = s[0];
    #pragma unroll
    for (int a = 1; a < 8; a++) mx = fmaxf(mx, s[a]);
    float w[8], wsum = 0.0f;
    #pragma unroll
    for (int a = 0; a < 8; a++) { w[a] = expf(s[a] - mx); wsum += w[a]; }
    const float inv = 1.0f / wsum;

    float o = 0.0f;
    #pragma unroll
    for (int a = 0; a < 8; a++) o += w[a] * vs[a][j];
    o *= inv;

    // multi_head_attention = tile(out2, (8,1)): row i = out2[i % 8192]
    #pragma unroll
    for (int t = 0; t < 8; t++)
        out[((size_t)(t * NGRP + g)) * 128 + j] = o;
}

// ============================================================================
extern "C" void kernel_launch(void* const* d_in, const int* in_sizes, int n_in,
                              void* d_out, int out_size)
{
    const float* obs = (const float*)d_in[0];
    const float* eW1 = (const float*)d_in[1];
    const float* eb1 = (const float*)d_in[2];
    const float* eW2 = (const float*)d_in[3];
    const float* eb2 = (const float*)d_in[4];
    const float* vW1 = (const float*)d_in[5];
    const float* vb1 = (const float*)d_in[6];
    const float* vW2 = (const float*)d_in[7];
    const float* vb2 = (const float*)d_in[8];
    const float* aW1 = (const float*)d_in[9];
    const float* ab1 = (const float*)d_in[10];
    const float* aW2 = (const float*)d_in[11];
    const float* ab2 = (const float*)d_in[12];

    float* out = (float*)d_out;                        // multi_head_attention
    float* AA  = out + (size_t)BATCHN * HIDD;          // agent_attention

    void *pe, *pv, *pav;
    cudaGetSymbolAddress(&pe,  g_e);
    cudaGetSymbolAddress(&pv,  g_v);
    cudaGetSymbolAddress(&pav, g_av);
    float* e_g  = (float*)pe;
    float* v_g  = (float*)pv;
    float* av_g = (float*)pav;

    const int smemEmbed = (32 * 128 + 128 * 128 + 64 * 36 + 64 * 132) * 4;   // 124928 B
    const int smemMlp   = (128 * 128 + 128 * 128 + 64 * 132 + 64 * 132) * 4; // 198656 B
    cudaFuncSetAttribute(mlp2_kernel<32, true>,
                         cudaFuncAttributeMaxDynamicSharedMemorySize, smemEmbed);
    cudaFuncSetAttribute(mlp2_kernel<128, false>,
                         cudaFuncAttributeMaxDynamicSharedMemorySize, smemMlp);

    // 1) neighbor embeddings: gather(obs) -> 30->128->128 tanh MLP
    mlp2_kernel<32, true><<<1184, 256, smemEmbed>>>(
        obs, eW1, eb1, eW2, eb2, e_g, 30, NROWS / 64);

    // 2) neighbor values: e -> 128->128->128 tanh MLP
    mlp2_kernel<128, false><<<1184, 256, smemMlp>>>(
        e_g, vW1, vb1, vW2, vb2, v_g, 128, NROWS / 64);

    // 3) per-batch softmax attention -> agent_attention (second output half)
    attn1_kernel<<<BATCHN, 128>>>(e_g, v_g, AA);

    // 4) agent values: AA -> 128->128->128 tanh MLP
    mlp2_kernel<128, false><<<1024, 256, smemMlp>>>(
        AA, aW1, ab1, aW2, ab2, av_g, 128, BATCHN / 64);

    // 5) per-group multi-head attention + x8 tiled replication (first half)
    mha_kernel<<<NGRP, 128>>>(AA, av_g, out);
}

// round 2
// speedup vs baseline: 1.5358x; 1.5358x over previous
#include <cuda_runtime.h>
#include <math.h>

#define BATCHN 65536
#define NROWS  (BATCHN * 8)    // 524288 neighbor rows
#define NGRP   8192
#define OBSD   114

// ---- scratch (static device globals; no runtime allocation) ----
__device__ float g_e [(size_t)NROWS  * 128];   // neighbor embeddings (256 MB)
__device__ float g_av[(size_t)BATCHN * 128];   // agent values        ( 32 MB)

__device__ __forceinline__ float fast_tanh(float x) {
    float y;
    asm("tanh.approx.f32 %0, %1;" : "=f"(y) : "f"(x));
    return y;
}

// 8 rows x 4 cols per-thread GEMM over a [128 x KP] smem tile vs [KP x 128] weights.
// xv loads are warp-broadcast (address independent of lane) -> 1-phase LDS.
template<int KP>
__device__ __forceinline__ void gemm_tile(const float* __restrict__ Xs, int xstr,
                                          const float* __restrict__ Ws,
                                          float acc[8][4], int tr, int colBase)
{
    #pragma unroll
    for (int r = 0; r < 8; r++)
        acc[r][0] = acc[r][1] = acc[r][2] = acc[r][3] = 0.0f;

    #pragma unroll 2
    for (int k = 0; k < KP; k += 4) {
        float4 xv[8];
        #pragma unroll
        for (int r = 0; r < 8; r++)
            xv[r] = *(const float4*)&Xs[(tr * 8 + r) * xstr + k];
        #pragma unroll
        for (int kk = 0; kk < 4; kk++) {
            float4 w = *(const float4*)&Ws[(k + kk) * 128 + colBase];
            #pragma unroll
            for (int r = 0; r < 8; r++) {
                float xs = (kk == 0) ? xv[r].x : (kk == 1) ? xv[r].y
                         : (kk == 2) ? xv[r].z : xv[r].w;
                acc[r][0] = fmaf(xs, w.x, acc[r][0]);
                acc[r][1] = fmaf(xs, w.y, acc[r][1]);
                acc[r][2] = fmaf(xs, w.z, acc[r][2]);
                acc[r][3] = fmaf(xs, w.w, acc[r][3]);
            }
        }
    }
}

// ============================================================================
// Embed MLP: gather(obs) -> tanh(30->128) -> tanh(128->128) -> g_e
// 512 threads, 128-row tiles. Weights persistent: W1s 16K + W2s 64K + Xs 16K + Hs 64K.
// ============================================================================
__global__ void __launch_bounds__(512, 1)
embed_kernel(const float* __restrict__ obs,
             const float* __restrict__ W1, const float* __restrict__ b1,
             const float* __restrict__ W2, const float* __restrict__ b2,
             float* __restrict__ Y, int nTiles)
{
    extern __shared__ float sm[];
    float* W1s = sm;                 // 32*128
    float* W2s = W1s + 32 * 128;     // 128*128
    float* Xs  = W2s + 128 * 128;    // 128*32
    float* Hs  = Xs  + 128 * 32;     // 128*128

    const int tid = threadIdx.x;
    const int tr = tid >> 5;
    const int colBase = (tid & 31) << 2;

    for (int i = tid; i < 32 * 128; i += 512)
        W1s[i] = (i < 30 * 128) ? W1[i] : 0.0f;
    for (int i = tid; i < 128 * 128 / 4; i += 512)
        ((float4*)W2s)[i] = ((const float4*)W2)[i];

    const float4 b1v = *(const float4*)(b1 + colBase);
    const float4 b2v = *(const float4*)(b2 + colBase);

    for (int tile = blockIdx.x; tile < nTiles; tile += gridDim.x) {
        const int row0 = tile * 128;

        // gather: row R -> [self_obs[R % 65536][0:18] | obs[R/8][18 + (R%8)*12 : +12]]
        for (int idx = tid; idx < 128 * 32; idx += 512) {
            int r = idx >> 5, k = idx & 31;
            int R = row0 + r;
            float val = 0.0f;
            if (k < 18)
                val = obs[(R & (BATCHN - 1)) * OBSD + k];
            else if (k < 30)
                val = obs[(R >> 3) * OBSD + 18 + (R & 7) * 12 + (k - 18)];
            Xs[r * 32 + k] = val;
        }
        __syncthreads();

        float acc[8][4];
        gemm_tile<32>(Xs, 32, W1s, acc, tr, colBase);
        #pragma unroll
        for (int r = 0; r < 8; r++) {
            float4 h;
            h.x = fast_tanh(acc[r][0] + b1v.x);
            h.y = fast_tanh(acc[r][1] + b1v.y);
            h.z = fast_tanh(acc[r][2] + b1v.z);
            h.w = fast_tanh(acc[r][3] + b1v.w);
            *(float4*)&Hs[(tr * 8 + r) * 128 + colBase] = h;
        }
        __syncthreads();

        gemm_tile<128>(Hs, 128, W2s, acc, tr, colBase);
        #pragma unroll
        for (int r = 0; r < 8; r++) {
            float4 o;
            o.x = fast_tanh(acc[r][0] + b2v.x);
            o.y = fast_tanh(acc[r][1] + b2v.y);
            o.z = fast_tanh(acc[r][2] + b2v.z);
            o.w = fast_tanh(acc[r][3] + b2v.w);
            *(float4*)&Y[(size_t)(row0 + tr * 8 + r) * 128 + colBase] = o;
        }
        // no sync needed: next gather writes Xs; all Xs reads finished before the
        // Hs-write barrier above, and concurrent Hs readers don't touch Xs.
    }
}

// ============================================================================
// Fused value-MLP + neighbor attention (ATTN=true), or plain agent MLP (false).
// X/H share one smem buffer (in-place). 8 rows/thread == one batch's 8 neighbors,
// so the attention combine happens entirely in registers.
//   ATTN: AA[b] = softmax_n( (mean_n e / sqrt128) . e[n] ) . v[n]   -> out
//   plain: out = tanh MLP output rows
// ============================================================================
template<bool ATTN>
__global__ void __launch_bounds__(512, 1)
mlp_kernel(const float* __restrict__ X,
           const float* __restrict__ W1, const float* __restrict__ b1,
           const float* __restrict__ W2, const float* __restrict__ b2,
           float* __restrict__ out, int nTiles)
{
    extern __shared__ float sm[];
    float* W1s = sm;                 // 128*128
    float* W2s = W1s + 128 * 128;    // 128*128
    float* XHs = W2s + 128 * 128;    // 128*128 shared X/H

    const int tid = threadIdx.x;
    const int tr = tid >> 5;
    const int colBase = (tid & 31) << 2;

    for (int i = tid; i < 128 * 128 / 4; i += 512) {
        ((float4*)W1s)[i] = ((const float4*)W1)[i];
        ((float4*)W2s)[i] = ((const float4*)W2)[i];
    }

    const float4 b1v = *(const float4*)(b1 + colBase);
    const float4 b2v = *(const float4*)(b2 + colBase);

    for (int tile = blockIdx.x; tile < nTiles; tile += gridDim.x) {
        const int row0 = tile * 128;

        __syncthreads();   // previous iteration's XHs readers done
        for (int i = tid; i < 128 * 128 / 4; i += 512)
            ((float4*)XHs)[i] = ((const float4*)(X + (size_t)row0 * 128))[i];
        __syncthreads();

        float acc[8][4];
        gemm_tile<128>(XHs, 128, W1s, acc, tr, colBase);

        float w8[8];
        if (ATTN) {
            // XHs still holds e for this tile; thread tr owns batch row0/8 + tr.
            float4 ev[8];
            #pragma unroll
            for (int n = 0; n < 8; n++)
                ev[n] = *(const float4*)&XHs[(tr * 8 + n) * 128 + colBase];
            float4 q;
            q.x = ev[0].x; q.y = ev[0].y; q.z = ev[0].z; q.w = ev[0].w;
            #pragma unroll
            for (int n = 1; n < 8; n++) {
                q.x += ev[n].x; q.y += ev[n].y; q.z += ev[n].z; q.w += ev[n].w;
            }
            const float qs = 0.011048543456039806f;   // 1/(8*sqrt(128))
            q.x *= qs; q.y *= qs; q.z *= qs; q.w *= qs;
            float s[8];
            #pragma unroll
            for (int n = 0; n < 8; n++) {
                float p = q.x * ev[n].x + q.y * ev[n].y + q.z * ev[n].z + q.w * ev[n].w;
                #pragma unroll
                for (int o = 16; o >= 1; o >>= 1)
                    p += __shfl_xor_sync(0xffffffff, p, o);
                s[n] = p;   // full 128-dim dot product
            }
            float mx = s[0];
            #pragma unroll
            for (int n = 1; n < 8; n++) mx = fmaxf(mx, s[n]);
            float wsum = 0.0f;
            #pragma unroll
            for (int n = 0; n < 8; n++) { w8[n] = expf(s[n] - mx); wsum += w8[n]; }
            const float inv = 1.0f / wsum;
            #pragma unroll
            for (int n = 0; n < 8; n++) w8[n] *= inv;
        }
        __syncthreads();   // all XHs reads done before overwrite

        #pragma unroll
        for (int r = 0; r < 8; r++) {
            float4 h;
            h.x = fast_tanh(acc[r][0] + b1v.x);
            h.y = fast_tanh(acc[r][1] + b1v.y);
            h.z = fast_tanh(acc[r][2] + b1v.z);
            h.w = fast_tanh(acc[r][3] + b1v.w);
            *(float4*)&XHs[(tr * 8 + r) * 128 + colBase] = h;
        }
        __syncthreads();

        gemm_tile<128>(XHs, 128, W2s, acc, tr, colBase);

        if (ATTN) {
            float4 o = make_float4(0.f, 0.f, 0.f, 0.f);
            #pragma unroll
            for (int n = 0; n < 8; n++) {
                o.x += w8[n] * fast_tanh(acc[n][0] + b2v.x);
                o.y += w8[n] * fast_tanh(acc[n][1] + b2v.y);
                o.z += w8[n] * fast_tanh(acc[n][2] + b2v.z);
                o.w += w8[n] * fast_tanh(acc[n][3] + b2v.w);
            }
            const int batch = (row0 >> 3) + tr;
            *(float4*)&out[(size_t)batch * 128 + colBase] = o;
        } else {
            #pragma unroll
            for (int r = 0; r < 8; r++) {
                float4 o;
                o.x = fast_tanh(acc[r][0] + b2v.x);
                o.y = fast_tanh(acc[r][1] + b2v.y);
                o.z = fast_tanh(acc[r][2] + b2v.z);
                o.w = fast_tanh(acc[r][3] + b2v.w);
                *(float4*)&out[(size_t)(row0 + tr * 8 + r) * 128 + colBase] = o;
            }
        }
    }
}

// ============================================================================
// Per-group multi-head attention (8 heads x 16 dims over 8 agents) + tile x8.
// ============================================================================
__global__ void __launch_bounds__(128)
mha_kernel(const float* __restrict__ AA,
           const float* __restrict__ AV,
           float* __restrict__ out)
{
    __shared__ float ks[8][128];
    __shared__ float vs[8][128];

    const int g = blockIdx.x;
    const int j = threadIdx.x;
    const size_t base = (size_t)g * 8 * 128;

    #pragma unroll
    for (int a = 0; a < 8; a++) {
        ks[a][j] = AA[base + a * 128 + j];
        vs[a][j] = AV[base + a * 128 + j];
    }
    __syncthreads();

    float q = 0.0f;
    #pragma unroll
    for (int a = 0; a < 8; a++) q += ks[a][j];
    q *= 0.03125f;                            // (1/8 mean) * (1/sqrt(16))

    float s[8];
    #pragma unroll
    for (int a = 0; a < 8; a++) {
        float p = q * ks[a][j];
        p += __shfl_xor_sync(0xffffffff, p, 8);
        p += __shfl_xor_sync(0xffffffff, p, 4);
        p += __shfl_xor_sync(0xffffffff, p, 2);
        p += __shfl_xor_sync(0xffffffff, p, 1);
        s[a] = p;
    }

    float mx = s[0];
    #pragma unroll
    for (int a = 1; a < 8; a++) mx = fmaxf(mx, s[a]);
    float w[8], wsum = 0.0f;
    #pragma unroll
    for (int a = 0; a < 8; a++) { w[a] = expf(s[a] - mx); wsum += w[a]; }
    const float inv = 1.0f / wsum;

    float o = 0.0f;
    #pragma unroll
    for (int a = 0; a < 8; a++) o += w[a] * vs[a][j];
    o *= inv;

    #pragma unroll
    for (int t = 0; t < 8; t++)
        out[((size_t)(t * NGRP + g)) * 128 + j] = o;
}

// ============================================================================
extern "C" void kernel_launch(void* const* d_in, const int* in_sizes, int n_in,
                              void* d_out, int out_size)
{
    const float* obs = (const float*)d_in[0];
    const float* eW1 = (const float*)d_in[1];
    const float* eb1 = (const float*)d_in[2];
    const float* eW2 = (const float*)d_in[3];
    const float* eb2 = (const float*)d_in[4];
    const float* vW1 = (const float*)d_in[5];
    const float* vb1 = (const float*)d_in[6];
    const float* vW2 = (const float*)d_in[7];
    const float* vb2 = (const float*)d_in[8];
    const float* aW1 = (const float*)d_in[9];
    const float* ab1 = (const float*)d_in[10];
    const float* aW2 = (const float*)d_in[11];
    const float* ab2 = (const float*)d_in[12];

    float* out = (float*)d_out;                        // multi_head_attention
    float* AA  = out + (size_t)BATCHN * 128;           // agent_attention

    void *pe, *pav;
    cudaGetSymbolAddress(&pe,  g_e);
    cudaGetSymbolAddress(&pav, g_av);
    float* e_g  = (float*)pe;
    float* av_g = (float*)pav;

    const int smemEmbed = (32 * 128 + 128 * 128 + 128 * 32 + 128 * 128) * 4;  // 163840
    const int smemMlp   = (3 * 128 * 128) * 4;                                // 196608
    cudaFuncSetAttribute(embed_kernel,
                         cudaFuncAttributeMaxDynamicSharedMemorySize, smemEmbed);
    cudaFuncSetAttribute(mlp_kernel<true>,
                         cudaFuncAttributeMaxDynamicSharedMemorySize, smemMlp);
    cudaFuncSetAttribute(mlp_kernel<false>,
                         cudaFuncAttributeMaxDynamicSharedMemorySize, smemMlp);

    // 1) neighbor embeddings: gather(obs) -> 30->128->128 tanh MLP -> g_e
    embed_kernel<<<148, 512, smemEmbed>>>(obs, eW1, eb1, eW2, eb2, e_g, NROWS / 128);

    // 2) value MLP fused with neighbor attention -> agent_attention (2nd output)
    mlp_kernel<true><<<148, 512, smemMlp>>>(e_g, vW1, vb1, vW2, vb2, AA, NROWS / 128);

    // 3) agent values: AA -> 128->128->128 tanh MLP -> g_av
    mlp_kernel<false><<<148, 512, smemMlp>>>(AA, aW1, ab1, aW2, ab2, av_g, BATCHN / 128);

    // 4) per-group multi-head attention + x8 tiled replication (1st output)
    mha_kernel<<<NGRP, 128>>>(AA, av_g, out);
}

// round 5
// speedup vs baseline: 4.0021x; 2.6059x over previous
#include <cuda_runtime.h>
#include <stdint.h>

#define BATCHN 65536
#define NROWS  (BATCHN * 8)
#define NGRP   8192
#define OBSD   114

__device__ float g_e [(size_t)NROWS  * 128];   // neighbor embeddings (256 MB)
__device__ float g_av[(size_t)BATCHN * 128];   // agent values        ( 32 MB)

__device__ __forceinline__ float fast_tanh(float x){float y;asm("tanh.approx.f32 %0,%1;":"=f"(y):"f"(x));return y;}
// tf32 destination must be .b32: output via "=r", reinterpret as float (valid fp32 value)
__device__ __forceinline__ float to_tf32(float x){uint32_t y;asm("cvt.rna.tf32.f32 %0,%1;":"=r"(y):"f"(x));return __uint_as_float(y);}

// m16n8k8 TF32 mma: D += A(16x8 row) * B(8x8 col)
__device__ __forceinline__ void mma8(float c[4], uint32_t a0, uint32_t a1, uint32_t a2, uint32_t a3,
                                     uint32_t b0, uint32_t b1){
    asm volatile("mma.sync.aligned.m16n8k8.row.col.f32.tf32.tf32.f32 "
                 "{%0,%1,%2,%3},{%4,%5,%6,%7},{%8,%9},{%0,%1,%2,%3};"
                 : "+f"(c[0]), "+f"(c[1]), "+f"(c[2]), "+f"(c[3])
                 : "r"(a0), "r"(a1), "r"(a2), "r"(a3), "r"(b0), "r"(b1));
}

// One layer: warp's 16-row slab (stride XS floats, tf32 values) x packed weights -> acc[16][4]
// Fragment layouts (PTX m16n8k8): A a0{r,c} a1{r+8,c} a2{r,c+4} a3{r+8,c+4}, r=lane>>2, c=lane&3
template<int KS>
__device__ __forceinline__ void mma_layer(const float* __restrict__ Xw, int XS,
                                          const float2* __restrict__ Wp,
                                          float acc[16][4], int lane){
    #pragma unroll
    for (int nt = 0; nt < 16; nt++){ acc[nt][0]=acc[nt][1]=acc[nt][2]=acc[nt][3]=0.f; }
    #pragma unroll 4
    for (int ks = 0; ks < KS; ks++){
        const float* ab = Xw + (lane >> 2) * XS + ks * 8 + (lane & 3);
        uint32_t a0 = __float_as_uint(ab[0]);
        uint32_t a1 = __float_as_uint(ab[8 * XS]);
        uint32_t a2 = __float_as_uint(ab[4]);
        uint32_t a3 = __float_as_uint(ab[8 * XS + 4]);
        #pragma unroll
        for (int nt = 0; nt < 16; nt++){
            float2 b = Wp[(ks * 16 + nt) * 32 + lane];
            mma8(acc[nt], a0, a1, a2, a3, __float_as_uint(b.x), __float_as_uint(b.y));
        }
    }
}

// Pack W[k][n] (row-major KxN=128) into per-fragment order: Wp[ks][nt][lane] = (W[k][n], W[k+4][n])
// with k = ks*8 + (lane&3), n = nt*8 + (lane>>2). One LDS.64 per B fragment at use time.
__device__ __forceinline__ void pack_w(const float* __restrict__ W, float2* __restrict__ Wp,
                                       int KS, int K, int tid){
    for (int f = tid; f < KS * 16 * 32; f += 256){
        int ks = f >> 9, nt = (f >> 5) & 15, lane = f & 31;
        int k = ks * 8 + (lane & 3), n = nt * 8 + (lane >> 2);
        float w0 = (k     < K) ? W[(size_t)k       * 128 + n] : 0.f;
        float w1 = (k + 4 < K) ? W[(size_t)(k + 4) * 128 + n] : 0.f;
        Wp[f] = make_float2(to_tf32(w0), to_tf32(w1));
    }
}

// ============================================================================
// Embed: gather(obs) -> tanh(30->128) -> tanh(128->128) -> g_e
// ============================================================================
#define EXS 36
__global__ void __launch_bounds__(256, 1)
embed_kernel(const float* __restrict__ obs,
             const float* __restrict__ W1, const float* __restrict__ b1,
             const float* __restrict__ W2, const float* __restrict__ b2,
             float* __restrict__ Y, int nTiles)
{
    extern __shared__ float sm[];
    float2* Wp1 = (float2*)sm;               // 2048 float2 (16 KB)
    float2* Wp2 = Wp1 + 2048;                // 8192 float2 (64 KB)
    float*  bsm = (float*)(Wp2 + 8192);      // 256
    float*  Xs  = bsm + 256;                 // 128*36
    float*  Hs  = Xs + 128 * EXS;            // 128*132

    const int tid = threadIdx.x, w = tid >> 5, lane = tid & 31;
    pack_w(W1, Wp1, 4, 30, tid);
    pack_w(W2, Wp2, 16, 128, tid);
    if (tid < 128){ bsm[tid] = b1[tid]; bsm[128 + tid] = b2[tid]; }
    __syncthreads();

    float* Xw = Xs + w * 16 * EXS;
    float* Hw = Hs + w * 16 * 132;
    const int r2 = lane >> 1, hh = lane & 1;

    for (int tile = blockIdx.x; tile < nTiles; tile += gridDim.x){
        const int row0 = tile * 128 + w * 16;
        {   // gather: 2 lanes per row; cols [0,18) self, [18,30) neighbor, [30,36) zero
            int R = row0 + r2;
            float* dst = Xw + r2 * EXS + hh * 18;
            if (hh == 0){
                const float* sp = obs + (size_t)(R & (BATCHN - 1)) * OBSD;
                #pragma unroll
                for (int j = 0; j < 18; j++) dst[j] = to_tf32(sp[j]);
            } else {
                const float* np = obs + (size_t)(R >> 3) * OBSD + 18 + (R & 7) * 12;
                #pragma unroll
                for (int j = 0; j < 12; j++) dst[j] = to_tf32(np[j]);
                #pragma unroll
                for (int j = 12; j < 18; j++) dst[j] = 0.f;
            }
        }
        __syncwarp();
        float acc[16][4];
        mma_layer<4>(Xw, EXS, Wp1, acc, lane);
        {   // epilogue 1 -> H (tf32)
            const int r = lane >> 2, t = lane & 3;
            #pragma unroll
            for (int nt = 0; nt < 16; nt++){
                int c = nt * 8 + t * 2;
                float2 v0, v1;
                v0.x = to_tf32(fast_tanh(acc[nt][0] + bsm[c]));
                v0.y = to_tf32(fast_tanh(acc[nt][1] + bsm[c + 1]));
                v1.x = to_tf32(fast_tanh(acc[nt][2] + bsm[c]));
                v1.y = to_tf32(fast_tanh(acc[nt][3] + bsm[c + 1]));
                *(float2*)(Hw + r * 132 + c) = v0;
                *(float2*)(Hw + (r + 8) * 132 + c) = v1;
            }
        }
        __syncwarp();
        mma_layer<16>(Hw, 132, Wp2, acc, lane);
        {   // epilogue 2 -> g_e (fp32)
            const int r = lane >> 2, t = lane & 3;
            float* y0 = Y + (size_t)(row0 + r) * 128;
            float* y1 = Y + (size_t)(row0 + r + 8) * 128;
            #pragma unroll
            for (int nt = 0; nt < 16; nt++){
                int c = nt * 8 + t * 2;
                float2 v0, v1;
                v0.x = fast_tanh(acc[nt][0] + bsm[128 + c]);
                v0.y = fast_tanh(acc[nt][1] + bsm[128 + c + 1]);
                v1.x = fast_tanh(acc[nt][2] + bsm[128 + c]);
                v1.y = fast_tanh(acc[nt][3] + bsm[128 + c + 1]);
                *(float2*)(y0 + c) = v0;
                *(float2*)(y1 + c) = v1;
            }
        }
        __syncwarp();
    }
}

// ============================================================================
// Value MLP fused with neighbor attention:
//   e -> h=tanh(e@vW1+b1) -> v=tanh(h@vW2+b2);  AA[b]=softmax(q.e/sqrt128).v
// Warp slab = 16 rows = 2 batches. No CTA barriers in the loop.
// ============================================================================
__global__ void __launch_bounds__(256, 1)
value_kernel(const float* __restrict__ X,
             const float* __restrict__ W1, const float* __restrict__ b1,
             const float* __restrict__ W2, const float* __restrict__ b2,
             float* __restrict__ AA, int nTiles)
{
    extern __shared__ float sm[];
    float2* Wp1 = (float2*)sm;               // 8192 float2
    float2* Wp2 = Wp1 + 8192;                // 8192 float2
    float*  bsm = (float*)(Wp2 + 8192);      // 256
    float*  XH  = bsm + 256;                 // 128*132 (X and H in place)

    const int tid = threadIdx.x, w = tid >> 5, lane = tid & 31;
    pack_w(W1, Wp1, 16, 128, tid);
    pack_w(W2, Wp2, 16, 128, tid);
    if (tid < 128){ bsm[tid] = b1[tid]; bsm[128 + tid] = b2[tid]; }
    __syncthreads();

    float* Xw = XH + w * 16 * 132;

    for (int tile = blockIdx.x; tile < nTiles; tile += gridDim.x){
        const int row0 = tile * 128 + w * 16;
        {   // load e slab (coalesced float4), cvt tf32
            const float4* src = (const float4*)(X + (size_t)row0 * 128);
            #pragma unroll
            for (int i = 0; i < 16; i++){
                int idx = i * 32 + lane; int r = idx >> 5, c4 = idx & 31;
                float4 u = src[idx];
                float* d = Xw + r * 132 + c4 * 4;
                d[0] = to_tf32(u.x); d[1] = to_tf32(u.y);
                d[2] = to_tf32(u.z); d[3] = to_tf32(u.w);
            }
        }
        __syncwarp();
        float acc[16][4];
        mma_layer<16>(Xw, 132, Wp1, acc, lane);

        // ---- attention weights from e (still in Xw) ----
        float w8[16];
        {
            float q0[4] = {0,0,0,0}, q1[4] = {0,0,0,0};
            #pragma unroll
            for (int r = 0; r < 8; r++){
                float4 u = *(const float4*)(Xw + r * 132 + lane * 4);
                q0[0]+=u.x; q0[1]+=u.y; q0[2]+=u.z; q0[3]+=u.w;
                float4 v = *(const float4*)(Xw + (r + 8) * 132 + lane * 4);
                q1[0]+=v.x; q1[1]+=v.y; q1[2]+=v.z; q1[3]+=v.w;
            }
            const float qs = 0.011048543456039806f;   // 1/(8*sqrt(128))
            #pragma unroll
            for (int j = 0; j < 4; j++){ q0[j] *= qs; q1[j] *= qs; }
            float p[16];
            #pragma unroll
            for (int r = 0; r < 16; r++){
                float4 u = *(const float4*)(Xw + r * 132 + lane * 4);
                const float* qq = (r < 8) ? q0 : q1;
                p[r] = qq[0]*u.x + qq[1]*u.y + qq[2]*u.z + qq[3]*u.w;
            }
            #pragma unroll
            for (int o = 16; o >= 1; o >>= 1)
                #pragma unroll
                for (int r = 0; r < 16; r++) p[r] += __shfl_xor_sync(0xffffffff, p[r], o);
            float mx0 = p[0], mx1 = p[8];
            #pragma unroll
            for (int r = 1; r < 8; r++){ mx0 = fmaxf(mx0, p[r]); mx1 = fmaxf(mx1, p[8+r]); }
            float s0 = 0.f, s1 = 0.f;
            #pragma unroll
            for (int r = 0; r < 8; r++){
                w8[r]   = __expf(p[r]   - mx0); s0 += w8[r];
                w8[8+r] = __expf(p[8+r] - mx1); s1 += w8[8+r];
            }
            float i0 = 1.f / s0, i1 = 1.f / s1;
            #pragma unroll
            for (int r = 0; r < 8; r++){ w8[r] *= i0; w8[8+r] *= i1; }
        }
        __syncwarp();   // all e reads done before in-place H overwrite

        {   // epilogue 1 -> H in place (tf32)
            const int r = lane >> 2, t = lane & 3;
            #pragma unroll
            for (int nt = 0; nt < 16; nt++){
                int c = nt * 8 + t * 2;
                float2 v0, v1;
                v0.x = to_tf32(fast_tanh(acc[nt][0] + bsm[c]));
                v0.y = to_tf32(fast_tanh(acc[nt][1] + bsm[c + 1]));
                v1.x = to_tf32(fast_tanh(acc[nt][2] + bsm[c]));
                v1.y = to_tf32(fast_tanh(acc[nt][3] + bsm[c + 1]));
                *(float2*)(Xw + r * 132 + c) = v0;
                *(float2*)(Xw + (r + 8) * 132 + c) = v1;
            }
        }
        __syncwarp();
        mma_layer<16>(Xw, 132, Wp2, acc, lane);

        {   // v = tanh(acc+b2); weighted sum over 8 neighbor rows -> AA
            const int r = lane >> 2, t = lane & 3;
            const float wA = w8[r], wB = w8[8 + r];
            float* outA = AA + (size_t)(row0 >> 3) * 128;
            float* outB = AA + (size_t)((row0 >> 3) + 1) * 128;
            #pragma unroll
            for (int nt = 0; nt < 16; nt++){
                int c = nt * 8 + t * 2;
                float a0 = fast_tanh(acc[nt][0] + bsm[128 + c])     * wA;
                float a1 = fast_tanh(acc[nt][1] + bsm[128 + c + 1]) * wA;
                float e0 = fast_tanh(acc[nt][2] + bsm[128 + c])     * wB;
                float e1 = fast_tanh(acc[nt][3] + bsm[128 + c + 1]) * wB;
                #pragma unroll
                for (int o = 4; o <= 16; o <<= 1){
                    a0 += __shfl_xor_sync(0xffffffff, a0, o);
                    a1 += __shfl_xor_sync(0xffffffff, a1, o);
                    e0 += __shfl_xor_sync(0xffffffff, e0, o);
                    e1 += __shfl_xor_sync(0xffffffff, e1, o);
                }
                if (lane < 4)       *(float2*)(outA + c) = make_float2(a0, a1);
                else if (lane < 8)  *(float2*)(outB + nt * 8 + (lane & 3) * 2) = make_float2(e0, e1);
            }
        }
        __syncwarp();
    }
}

// ============================================================================
// Agent MLP: AA -> tanh(128->128) -> tanh(128->128) -> g_av
// ============================================================================
__global__ void __launch_bounds__(256, 1)
agent_kernel(const float* __restrict__ X,
             const float* __restrict__ W1, const float* __restrict__ b1,
             const float* __restrict__ W2, const float* __restrict__ b2,
             float* __restrict__ Y, int nTiles)
{
    extern __shared__ float sm[];
    float2* Wp1 = (float2*)sm;
    float2* Wp2 = Wp1 + 8192;
    float*  bsm = (float*)(Wp2 + 8192);
    float*  XH  = bsm + 256;

    const int tid = threadIdx.x, w = tid >> 5, lane = tid & 31;
    pack_w(W1, Wp1, 16, 128, tid);
    pack_w(W2, Wp2, 16, 128, tid);
    if (tid < 128){ bsm[tid] = b1[tid]; bsm[128 + tid] = b2[tid]; }
    __syncthreads();

    float* Xw = XH + w * 16 * 132;

    for (int tile = blockIdx.x; tile < nTiles; tile += gridDim.x){
        const int row0 = tile * 128 + w * 16;
        {
            const float4* src = (const float4*)(X + (size_t)row0 * 128);
            #pragma unroll
            for (int i = 0; i < 16; i++){
                int idx = i * 32 + lane; int r = idx >> 5, c4 = idx & 31;
                float4 u = src[idx];
                float* d = Xw + r * 132 + c4 * 4;
                d[0] = to_tf32(u.x); d[1] = to_tf32(u.y);
                d[2] = to_tf32(u.z); d[3] = to_tf32(u.w);
            }
        }
        __syncwarp();
        float acc[16][4];
        mma_layer<16>(Xw, 132, Wp1, acc, lane);
        {
            const int r = lane >> 2, t = lane & 3;
            #pragma unroll
            for (int nt = 0; nt < 16; nt++){
                int c = nt * 8 + t * 2;
                float2 v0, v1;
                v0.x = to_tf32(fast_tanh(acc[nt][0] + bsm[c]));
                v0.y = to_tf32(fast_tanh(acc[nt][1] + bsm[c + 1]));
                v1.x = to_tf32(fast_tanh(acc[nt][2] + bsm[c]));
                v1.y = to_tf32(fast_tanh(acc[nt][3] + bsm[c + 1]));
                *(float2*)(Xw + r * 132 + c) = v0;
                *(float2*)(Xw + (r + 8) * 132 + c) = v1;
            }
        }
        __syncwarp();
        mma_layer<16>(Xw, 132, Wp2, acc, lane);
        {
            const int r = lane >> 2, t = lane & 3;
            float* y0 = Y + (size_t)(row0 + r) * 128;
            float* y1 = Y + (size_t)(row0 + r + 8) * 128;
            #pragma unroll
            for (int nt = 0; nt < 16; nt++){
                int c = nt * 8 + t * 2;
                float2 v0, v1;
                v0.x = fast_tanh(acc[nt][0] + bsm[128 + c]);
                v0.y = fast_tanh(acc[nt][1] + bsm[128 + c + 1]);
                v1.x = fast_tanh(acc[nt][2] + bsm[128 + c]);
                v1.y = fast_tanh(acc[nt][3] + bsm[128 + c + 1]);
                *(float2*)(y0 + c) = v0;
                *(float2*)(y1 + c) = v1;
            }
        }
        __syncwarp();
    }
}

// ============================================================================
// Per-group multi-head attention (8 heads x 16 dims over 8 agents) + tile x8.
// ============================================================================
__global__ void __launch_bounds__(128)
mha_kernel(const float* __restrict__ AA, const float* __restrict__ AV,
           float* __restrict__ out)
{
    __shared__ float ks[8][128];
    __shared__ float vs[8][128];
    const int g = blockIdx.x;
    const int j = threadIdx.x;
    const size_t base = (size_t)g * 8 * 128;

    #pragma unroll
    for (int a = 0; a < 8; a++){
        ks[a][j] = AA[base + a * 128 + j];
        vs[a][j] = AV[base + a * 128 + j];
    }
    __syncthreads();

    float q = 0.0f;
    #pragma unroll
    for (int a = 0; a < 8; a++) q += ks[a][j];
    q *= 0.03125f;                            // mean(1/8) * rsqrt(16)

    float s[8];
    #pragma unroll
    for (int a = 0; a < 8; a++){
        float p = q * ks[a][j];
        p += __shfl_xor_sync(0xffffffff, p, 8);
        p += __shfl_xor_sync(0xffffffff, p, 4);
        p += __shfl_xor_sync(0xffffffff, p, 2);
        p += __shfl_xor_sync(0xffffffff, p, 1);
        s[a] = p;
    }
    float mx = s[0];
    #pragma unroll
    for (int a = 1; a < 8; a++) mx = fmaxf(mx, s[a]);
    float wv[8], wsum = 0.0f;
    #pragma unroll
    for (int a = 0; a < 8; a++){ wv[a] = __expf(s[a] - mx); wsum += wv[a]; }
    const float inv = 1.0f / wsum;

    float o = 0.0f;
    #pragma unroll
    for (int a = 0; a < 8; a++) o += wv[a] * vs[a][j];
    o *= inv;

    #pragma unroll
    for (int t = 0; t < 8; t++)
        out[((size_t)(t * NGRP + g)) * 128 + j] = o;
}

// ============================================================================
extern "C" void kernel_launch(void* const* d_in, const int* in_sizes, int n_in,
                              void* d_out, int out_size)
{
    const float* obs = (const float*)d_in[0];
    const float* eW1 = (const float*)d_in[1];
    const float* eb1 = (const float*)d_in[2];
    const float* eW2 = (const float*)d_in[3];
    const float* eb2 = (const float*)d_in[4];
    const float* vW1 = (const float*)d_in[5];
    const float* vb1 = (const float*)d_in[6];
    const float* vW2 = (const float*)d_in[7];
    const float* vb2 = (const float*)d_in[8];
    const float* aW1 = (const float*)d_in[9];
    const float* ab1 = (const float*)d_in[10];
    const float* aW2 = (const float*)d_in[11];
    const float* ab2 = (const float*)d_in[12];

    float* out = (float*)d_out;                 // multi_head_attention
    float* AA  = out + (size_t)BATCHN * 128;    // agent_attention

    void *pe, *pav;
    cudaGetSymbolAddress(&pe,  g_e);
    cudaGetSymbolAddress(&pav, g_av);
    float* e_g  = (float*)pe;
    float* av_g = (float*)pav;

    const int smemE = (2048 + 8192) * 8 + 256 * 4 + 128 * EXS * 4 + 128 * 132 * 4; // 168960
    const int smemV = 8192 * 2 * 8 + 256 * 4 + 128 * 132 * 4;                      // 199680
    cudaFuncSetAttribute(embed_kernel, cudaFuncAttributeMaxDynamicSharedMemorySize, smemE);
    cudaFuncSetAttribute(value_kernel, cudaFuncAttributeMaxDynamicSharedMemorySize, smemV);
    cudaFuncSetAttribute(agent_kernel, cudaFuncAttributeMaxDynamicSharedMemorySize, smemV);

    embed_kernel<<<148, 256, smemE>>>(obs, eW1, eb1, eW2, eb2, e_g, NROWS / 128);
    value_kernel<<<148, 256, smemV>>>(e_g, vW1, vb1, vW2, vb2, AA, NROWS / 128);
    agent_kernel<<<148, 256, smemV>>>(AA, aW1, ab1, aW2, ab2, av_g, BATCHN / 128);
    mha_kernel<<<NGRP, 128>>>(AA, av_g, out);
}

// round 6
// speedup vs baseline: 5.2833x; 1.3201x over previous
#include <cuda_runtime.h>
#include <cuda_fp16.h>
#include <stdint.h>

#define BATCHN 65536
#define NROWS  (BATCHN * 8)
#define NGRP   8192
#define OBSD   114

__device__ __half g_av[(size_t)BATCHN * 128];   // agent values, fp16 (16 MB)

__device__ __forceinline__ float fast_tanh(float x){float y;asm("tanh.approx.f32 %0,%1;":"=f"(y):"f"(x));return y;}
// accurate tanh for output layers: rel err ~1e-6 (vs ~5e-4 for tanh.approx)
__device__ __forceinline__ float tanh_acc(float x){ return 1.f - __fdividef(2.f, __expf(2.f * x) + 1.f); }
__device__ __forceinline__ uint32_t pack2(float a, float b){ __half2 h = __floats2half2_rn(a, b); return *(uint32_t*)&h; }

// m16n8k16 fp16 mma, fp32 accumulate
__device__ __forceinline__ void mma16(float c[4], uint32_t a0, uint32_t a1, uint32_t a2, uint32_t a3,
                                      uint32_t b0, uint32_t b1){
    asm volatile("mma.sync.aligned.m16n8k16.row.col.f32.f16.f16.f32 "
                 "{%0,%1,%2,%3},{%4,%5,%6,%7},{%8,%9},{%0,%1,%2,%3};"
                 : "+f"(c[0]), "+f"(c[1]), "+f"(c[2]), "+f"(c[3])
                 : "r"(a0), "r"(a1), "r"(a2), "r"(a3), "r"(b0), "r"(b1));
}

// Warp 16-row slab (half, stride XS halves) x packed weights -> acc[16][4] (fp32)
// A frags (g=lane>>2, t=lane&3): a0 (g, 2t..2t+1), a1 (g+8, same), a2 (g, 2t+8..9), a3 (g+8, same)
template<int KS>
__device__ __forceinline__ void mma_layer(const __half* __restrict__ Xh, int XS,
                                          const uint2* __restrict__ Wp,
                                          float acc[16][4], int lane){
    const int g = lane >> 2, t = lane & 3;
    #pragma unroll
    for (int nt = 0; nt < 16; nt++){ acc[nt][0]=acc[nt][1]=acc[nt][2]=acc[nt][3]=0.f; }
    #pragma unroll
    for (int ks = 0; ks < KS; ks++){
        const __half* ab = Xh + g * XS + ks * 16 + 2 * t;
        uint32_t a0 = *(const uint32_t*)ab;
        uint32_t a1 = *(const uint32_t*)(ab + 8 * XS);
        uint32_t a2 = *(const uint32_t*)(ab + 8);
        uint32_t a3 = *(const uint32_t*)(ab + 8 * XS + 8);
        #pragma unroll
        for (int nt = 0; nt < 16; nt++){
            uint2 b = Wp[(ks * 16 + nt) * 32 + lane];
            mma16(acc[nt], a0, a1, a2, a3, b.x, b.y);
        }
    }
}

// Pack W[k][n] (row-major K x 128, fp32) into fp16 B-fragment order:
// Wp[(ks*16+nt)*32+lane] = uint2{ (W[k0][n],W[k0+1][n]), (W[k0+8][n],W[k0+9][n]) },
// k0 = ks*16 + 2t, n = nt*8 + g.
__device__ __forceinline__ void pack_w(const float* __restrict__ W, uint2* __restrict__ Wp,
                                       int KS, int K, int tid, int nthr){
    for (int f = tid; f < KS * 16 * 32; f += nthr){
        int ks = f >> 9, nt = (f >> 5) & 15, lane = f & 31;
        int g = lane >> 2, t = lane & 3;
        int n = nt * 8 + g;
        int k0 = ks * 16 + 2 * t, k1 = k0 + 8;
        float w00 = (k0     < K) ? W[(size_t)k0       * 128 + n] : 0.f;
        float w01 = (k0 + 1 < K) ? W[(size_t)(k0 + 1) * 128 + n] : 0.f;
        float w10 = (k1     < K) ? W[(size_t)k1       * 128 + n] : 0.f;
        float w11 = (k1 + 1 < K) ? W[(size_t)(k1 + 1) * 128 + n] : 0.f;
        Wp[f] = make_uint2(pack2(w00, w01), pack2(w10, w11));
    }
}

// half epilogue write: acc + bias -> tanh -> half2 into slab
#define EPI_H(Xw, XS, acc, bsm, boff, TANH) do { \
    const int g_ = lane >> 2, t_ = lane & 3; \
    _Pragma("unroll") \
    for (int nt = 0; nt < 16; nt++){ \
        int c = nt * 8 + 2 * t_; \
        *(__half2*)((Xw) + g_ * (XS) + c) = \
            __floats2half2_rn(TANH(acc[nt][0] + bsm[(boff) + c]), TANH(acc[nt][1] + bsm[(boff) + c + 1])); \
        *(__half2*)((Xw) + (g_ + 8) * (XS) + c) = \
            __floats2half2_rn(TANH(acc[nt][2] + bsm[(boff) + c]), TANH(acc[nt][3] + bsm[(boff) + c + 1])); \
    } \
} while(0)

// ============================================================================
// FUSED: gather(obs) -> embed MLP -> attn scores -> value MLP -> softmax
// combine -> agent_attention. Warp slab = 16 rows = 2 batches; e never
// leaves smem. XS = 136 halves (272B rows: conflict-free A frags).
// ============================================================================
#define XS 136
__global__ void __launch_bounds__(256, 1)
fused_ev_kernel(const float* __restrict__ obs,
                const float* __restrict__ eW1, const float* __restrict__ eb1,
                const float* __restrict__ eW2, const float* __restrict__ eb2,
                const float* __restrict__ vW1, const float* __restrict__ vb1,
                const float* __restrict__ vW2, const float* __restrict__ vb2,
                float* __restrict__ AA, int nTiles)
{
    extern __shared__ char sm[];
    uint2*  Wp1e = (uint2*)sm;                       //  8 KB (KS=2)
    uint2*  Wp2e = (uint2*)(sm + 8192);              // 32 KB
    uint2*  Wp1v = (uint2*)(sm + 40960);             // 32 KB
    uint2*  Wp2v = (uint2*)(sm + 73728);             // 32 KB
    float*  bsm  = (float*)(sm + 106496);            // 512 floats
    __half* XH   = (__half*)(sm + 108544);           // 8 warps x 16 x 136

    const int tid = threadIdx.x, w = tid >> 5, lane = tid & 31;
    pack_w(eW1, Wp1e, 2, 30, tid, 256);
    pack_w(eW2, Wp2e, 8, 128, tid, 256);
    pack_w(vW1, Wp1v, 8, 128, tid, 256);
    pack_w(vW2, Wp2v, 8, 128, tid, 256);
    if (tid < 128){
        bsm[tid] = eb1[tid]; bsm[128 + tid] = eb2[tid];
        bsm[256 + tid] = vb1[tid]; bsm[384 + tid] = vb2[tid];
    }
    __syncthreads();

    __half* Xw = XH + w * 16 * XS;
    const int r2 = lane >> 1, hh = lane & 1;

    for (int tile = blockIdx.x; tile < nTiles; tile += gridDim.x){
        const int row0 = tile * 128 + w * 16;

        {   // ---- gather: row R = [self[0:18] | nbr[0:12] | 0,0], fp16 ----
            int R = row0 + r2;
            __half* dst = Xw + r2 * XS;
            if (hh == 0){
                const float* sp = obs + (size_t)(R & (BATCHN - 1)) * OBSD;
                #pragma unroll
                for (int j = 0; j < 16; j++) dst[j] = __float2half_rn(sp[j]);
            } else {
                const float* sp = obs + (size_t)(R & (BATCHN - 1)) * OBSD;
                const float* np = obs + (size_t)(R >> 3) * OBSD + 18 + (R & 7) * 12;
                dst[16] = __float2half_rn(sp[16]);
                dst[17] = __float2half_rn(sp[17]);
                #pragma unroll
                for (int j = 0; j < 12; j++) dst[18 + j] = __float2half_rn(np[j]);
                dst[30] = __float2half_rn(0.f); dst[31] = __float2half_rn(0.f);
            }
        }
        __syncwarp();

        float acc[16][4];
        mma_layer<2>(Xw, XS, Wp1e, acc, lane);            // embed L1 (K=32)
        __syncwarp();
        EPI_H(Xw, XS, acc, bsm, 0, fast_tanh);
        __syncwarp();
        mma_layer<8>(Xw, XS, Wp2e, acc, lane);            // embed L2 -> e (in acc)
        __syncwarp();
        EPI_H(Xw, XS, acc, bsm, 128, fast_tanh);          // e -> smem (fp16)
        __syncwarp();

        // ---- attention weights from e ----
        float w8[16];
        {
            float q0[4] = {0,0,0,0}, q1[4] = {0,0,0,0};
            #pragma unroll
            for (int r = 0; r < 8; r++){
                uint2 u = *(const uint2*)(Xw + r * XS + lane * 4);
                float2 f0 = __half22float2(*(__half2*)&u.x), f1 = __half22float2(*(__half2*)&u.y);
                q0[0]+=f0.x; q0[1]+=f0.y; q0[2]+=f1.x; q0[3]+=f1.y;
                uint2 v = *(const uint2*)(Xw + (r + 8) * XS + lane * 4);
                float2 g0 = __half22float2(*(__half2*)&v.x), g1 = __half22float2(*(__half2*)&v.y);
                q1[0]+=g0.x; q1[1]+=g0.y; q1[2]+=g1.x; q1[3]+=g1.y;
            }
            const float qs = 0.011048543456039806f;       // 1/(8*sqrt(128))
            #pragma unroll
            for (int j = 0; j < 4; j++){ q0[j] *= qs; q1[j] *= qs; }
            float p[16];
            #pragma unroll
            for (int r = 0; r < 16; r++){
                uint2 u = *(const uint2*)(Xw + r * XS + lane * 4);
                float2 f0 = __half22float2(*(__half2*)&u.x), f1 = __half22float2(*(__half2*)&u.y);
                const float* qq = (r < 8) ? q0 : q1;
                p[r] = qq[0]*f0.x + qq[1]*f0.y + qq[2]*f1.x + qq[3]*f1.y;
            }
            #pragma unroll
            for (int o = 16; o >= 1; o >>= 1)
                #pragma unroll
                for (int r = 0; r < 16; r++) p[r] += __shfl_xor_sync(0xffffffff, p[r], o);
            float mx0 = p[0], mx1 = p[8];
            #pragma unroll
            for (int r = 1; r < 8; r++){ mx0 = fmaxf(mx0, p[r]); mx1 = fmaxf(mx1, p[8+r]); }
            float s0 = 0.f, s1 = 0.f;
            #pragma unroll
            for (int r = 0; r < 8; r++){
                w8[r]   = __expf(p[r]   - mx0); s0 += w8[r];
                w8[8+r] = __expf(p[8+r] - mx1); s1 += w8[8+r];
            }
            float i0 = 1.f / s0, i1 = 1.f / s1;
            #pragma unroll
            for (int r = 0; r < 8; r++){ w8[r] *= i0; w8[8+r] *= i1; }
        }
        __syncwarp();

        mma_layer<8>(Xw, XS, Wp1v, acc, lane);            // value L1 (reads e)
        __syncwarp();
        EPI_H(Xw, XS, acc, bsm, 256, fast_tanh);          // H over e
        __syncwarp();
        mma_layer<8>(Xw, XS, Wp2v, acc, lane);            // value L2

        {   // ---- v = tanh_acc(acc+b); weighted sum over 8 neighbors -> AA ----
            const int g = lane >> 2, t = lane & 3;
            const float wA = w8[g], wB = w8[8 + g];
            float* outA = AA + (size_t)(row0 >> 3) * 128;
            float* outB = AA + (size_t)((row0 >> 3) + 1) * 128;
            #pragma unroll
            for (int nt = 0; nt < 16; nt++){
                int c = nt * 8 + 2 * t;
                float a0 = tanh_acc(acc[nt][0] + bsm[384 + c])     * wA;
                float a1 = tanh_acc(acc[nt][1] + bsm[384 + c + 1]) * wA;
                float e0 = tanh_acc(acc[nt][2] + bsm[384 + c])     * wB;
                float e1 = tanh_acc(acc[nt][3] + bsm[384 + c + 1]) * wB;
                #pragma unroll
                for (int o = 4; o <= 16; o <<= 1){
                    a0 += __shfl_xor_sync(0xffffffff, a0, o);
                    a1 += __shfl_xor_sync(0xffffffff, a1, o);
                    e0 += __shfl_xor_sync(0xffffffff, e0, o);
                    e1 += __shfl_xor_sync(0xffffffff, e1, o);
                }
                if (lane < 4)       *(float2*)(outA + c) = make_float2(a0, a1);
                else if (lane < 8)  *(float2*)(outB + nt * 8 + (lane & 3) * 2) = make_float2(e0, e1);
            }
        }
        __syncwarp();
    }
}

// ============================================================================
// Agent MLP: AA (fp32) -> tanh(128->128) -> tanh(128->128) -> g_av (fp16)
// ============================================================================
__global__ void __launch_bounds__(256, 1)
agent_kernel(const float* __restrict__ X,
             const float* __restrict__ W1, const float* __restrict__ b1,
             const float* __restrict__ W2, const float* __restrict__ b2,
             __half* __restrict__ Y, int nTiles)
{
    extern __shared__ char sm[];
    uint2*  Wp1 = (uint2*)sm;                        // 32 KB
    uint2*  Wp2 = (uint2*)(sm + 32768);              // 32 KB
    float*  bsm = (float*)(sm + 65536);              // 256 floats
    __half* XH  = (__half*)(sm + 66560);

    const int tid = threadIdx.x, w = tid >> 5, lane = tid & 31;
    pack_w(W1, Wp1, 8, 128, tid, 256);
    pack_w(W2, Wp2, 8, 128, tid, 256);
    if (tid < 128){ bsm[tid] = b1[tid]; bsm[128 + tid] = b2[tid]; }
    __syncthreads();

    __half* Xw = XH + w * 16 * XS;

    for (int tile = blockIdx.x; tile < nTiles; tile += gridDim.x){
        const int row0 = tile * 128 + w * 16;
        {   // load slab fp32 -> fp16 smem
            const float4* src = (const float4*)(X + (size_t)row0 * 128);
            #pragma unroll
            for (int i = 0; i < 16; i++){
                int idx = i * 32 + lane; int r = idx >> 5, c4 = idx & 31;
                float4 u = src[idx];
                *(__half2*)(Xw + r * XS + c4 * 4)     = __floats2half2_rn(u.x, u.y);
                *(__half2*)(Xw + r * XS + c4 * 4 + 2) = __floats2half2_rn(u.z, u.w);
            }
        }
        __syncwarp();
        float acc[16][4];
        mma_layer<8>(Xw, XS, Wp1, acc, lane);
        __syncwarp();
        EPI_H(Xw, XS, acc, bsm, 0, fast_tanh);
        __syncwarp();
        mma_layer<8>(Xw, XS, Wp2, acc, lane);
        {   // output fp16
            const int g = lane >> 2, t = lane & 3;
            __half* y0 = Y + (size_t)(row0 + g) * 128;
            __half* y1 = Y + (size_t)(row0 + g + 8) * 128;
            #pragma unroll
            for (int nt = 0; nt < 16; nt++){
                int c = nt * 8 + 2 * t;
                *(__half2*)(y0 + c) = __floats2half2_rn(tanh_acc(acc[nt][0] + bsm[128 + c]),
                                                        tanh_acc(acc[nt][1] + bsm[128 + c + 1]));
                *(__half2*)(y1 + c) = __floats2half2_rn(tanh_acc(acc[nt][2] + bsm[128 + c]),
                                                        tanh_acc(acc[nt][3] + bsm[128 + c + 1]));
            }
        }
        __syncwarp();
    }
}

// ============================================================================
// Per-group multi-head attention (8 heads x 16 dims over 8 agents) + tile x8.
// ============================================================================
__global__ void __launch_bounds__(128)
mha_kernel(const float* __restrict__ AA, const __half* __restrict__ AV,
           float* __restrict__ out)
{
    __shared__ float ks[8][128];
    __shared__ float vs[8][128];
    const int g = blockIdx.x;
    const int j = threadIdx.x;
    const size_t base = (size_t)g * 8 * 128;

    #pragma unroll
    for (int a = 0; a < 8; a++){
        ks[a][j] = AA[base + a * 128 + j];
        vs[a][j] = __half2float(AV[base + a * 128 + j]);
    }
    __syncthreads();

    float q = 0.0f;
    #pragma unroll
    for (int a = 0; a < 8; a++) q += ks[a][j];
    q *= 0.03125f;                            // mean(1/8) * rsqrt(16)

    float s[8];
    #pragma unroll
    for (int a = 0; a < 8; a++){
        float p = q * ks[a][j];
        p += __shfl_xor_sync(0xffffffff, p, 8);
        p += __shfl_xor_sync(0xffffffff, p, 4);
        p += __shfl_xor_sync(0xffffffff, p, 2);
        p += __shfl_xor_sync(0xffffffff, p, 1);
        s[a] = p;
    }
    float mx = s[0];
    #pragma unroll
    for (int a = 1; a < 8; a++) mx = fmaxf(mx, s[a]);
    float wv[8], wsum = 0.0f;
    #pragma unroll
    for (int a = 0; a < 8; a++){ wv[a] = __expf(s[a] - mx); wsum += wv[a]; }
    const float inv = 1.0f / wsum;

    float o = 0.0f;
    #pragma unroll
    for (int a = 0; a < 8; a++) o += wv[a] * vs[a][j];
    o *= inv;

    #pragma unroll
    for (int t = 0; t < 8; t++)
        out[((size_t)(t * NGRP + g)) * 128 + j] = o;
}

// ============================================================================
extern "C" void kernel_launch(void* const* d_in, const int* in_sizes, int n_in,
                              void* d_out, int out_size)
{
    const float* obs = (const float*)d_in[0];
    const float* eW1 = (const float*)d_in[1];
    const float* eb1 = (const float*)d_in[2];
    const float* eW2 = (const float*)d_in[3];
    const float* eb2 = (const float*)d_in[4];
    const float* vW1 = (const float*)d_in[5];
    const float* vb1 = (const float*)d_in[6];
    const float* vW2 = (const float*)d_in[7];
    const float* vb2 = (const float*)d_in[8];
    const float* aW1 = (const float*)d_in[9];
    const float* ab1 = (const float*)d_in[10];
    const float* aW2 = (const float*)d_in[11];
    const float* ab2 = (const float*)d_in[12];

    float* out = (float*)d_out;                 // multi_head_attention
    float* AA  = out + (size_t)BATCHN * 128;    // agent_attention

    void* pav; cudaGetSymbolAddress(&pav, g_av);
    __half* av_g = (__half*)pav;

    const int smemF = 108544 + 8 * 16 * XS * 2;   // 143360
    const int smemA = 66560  + 8 * 16 * XS * 2;   // 101376
    cudaFuncSetAttribute(fused_ev_kernel, cudaFuncAttributeMaxDynamicSharedMemorySize, smemF);
    cudaFuncSetAttribute(agent_kernel,    cudaFuncAttributeMaxDynamicSharedMemorySize, smemA);

    fused_ev_kernel<<<148, 256, smemF>>>(obs, eW1, eb1, eW2, eb2,
                                         vW1, vb1, vW2, vb2, AA, NROWS / 128);
    agent_kernel<<<148, 256, smemA>>>(AA, aW1, ab1, aW2, ab2, av_g, BATCHN / 128);
    mha_kernel<<<NGRP, 128>>>(AA, av_g, out);
}

// round 7
// speedup vs baseline: 6.7252x; 1.2729x over previous
#include <cuda_runtime.h>
#include <cuda_fp16.h>
#include <stdint.h>

#define BATCHN 65536
#define NROWS  (BATCHN * 8)
#define NGRP   8192
#define OBSD   114
#define XS     136   // slab stride in halves (272B rows, conflict-free frags)

__device__ __half g_av[(size_t)BATCHN * 128];   // agent values, fp16 (16 MB)

__device__ __forceinline__ float fast_tanh(float x){float y;asm("tanh.approx.f32 %0,%1;":"=f"(y):"f"(x));return y;}
__device__ __forceinline__ float tanh_acc(float x){ return 1.f - __fdividef(2.f, __expf(2.f * x) + 1.f); }
__device__ __forceinline__ uint32_t pack2(float a, float b){ __half2 h = __floats2half2_rn(a, b); return *(uint32_t*)&h; }

#define BARS(id) asm volatile("bar.sync %0, 64;" :: "r"(id) : "memory")

// m16n8k16 fp16 mma, fp32 accumulate
__device__ __forceinline__ void mma16(float c[4], uint32_t a0, uint32_t a1, uint32_t a2, uint32_t a3,
                                      uint32_t b0, uint32_t b1){
    asm volatile("mma.sync.aligned.m16n8k16.row.col.f32.f16.f16.f32 "
                 "{%0,%1,%2,%3},{%4,%5,%6,%7},{%8,%9},{%0,%1,%2,%3};"
                 : "+f"(c[0]), "+f"(c[1]), "+f"(c[2]), "+f"(c[3])
                 : "r"(a0), "r"(a1), "r"(a2), "r"(a3), "r"(b0), "r"(b1));
}

// Warp computes 16 rows x 64 cols (its column half). Wc = Wp4 + c*128.
// Wp4 layout: [(ks*8 + ntp)*32 + lane] = uint4{b(nt=2ntp).xy, b(nt=2ntp+1).xy}
template<int KS>
__device__ __forceinline__ void mma_half(const __half* __restrict__ Xh,
                                         const uint4* __restrict__ Wc,
                                         float acc[8][4], int lane){
    const int g = lane >> 2, t = lane & 3;
    #pragma unroll
    for (int l = 0; l < 8; l++){ acc[l][0]=acc[l][1]=acc[l][2]=acc[l][3]=0.f; }
    #pragma unroll
    for (int ks = 0; ks < KS; ks++){
        const __half* ab = Xh + g * XS + ks * 16 + 2 * t;
        uint32_t a0 = *(const uint32_t*)ab;
        uint32_t a1 = *(const uint32_t*)(ab + 8 * XS);
        uint32_t a2 = *(const uint32_t*)(ab + 8);
        uint32_t a3 = *(const uint32_t*)(ab + 8 * XS + 8);
        #pragma unroll
        for (int j = 0; j < 4; j++){
            uint4 b = Wc[ks * 256 + j * 32 + lane];
            mma16(acc[2*j],     a0, a1, a2, a3, b.x, b.y);
            mma16(acc[2*j + 1], a0, a1, a2, a3, b.z, b.w);
        }
    }
}

// Pack W[k][n] (row-major K x 128 fp32) into uint4 B-fragment-pair order.
__device__ __forceinline__ void pack_w4(const float* __restrict__ W, uint4* __restrict__ Wp,
                                        int KS, int K, int tid, int nthr){
    for (int f = tid; f < KS * 8 * 32; f += nthr){
        int ks = f >> 8, ntp = (f >> 5) & 7, lane = f & 31;
        int g = lane >> 2, t = lane & 3;
        int n0 = ntp * 16 + g, n1 = n0 + 8;
        int k0 = ks * 16 + 2 * t, k1 = k0 + 8;
        float a00 = (k0     < K) ? W[(size_t)k0       * 128 + n0] : 0.f;
        float a01 = (k0 + 1 < K) ? W[(size_t)(k0 + 1) * 128 + n0] : 0.f;
        float a10 = (k1     < K) ? W[(size_t)k1       * 128 + n0] : 0.f;
        float a11 = (k1 + 1 < K) ? W[(size_t)(k1 + 1) * 128 + n0] : 0.f;
        float b00 = (k0     < K) ? W[(size_t)k0       * 128 + n1] : 0.f;
        float b01 = (k0 + 1 < K) ? W[(size_t)(k0 + 1) * 128 + n1] : 0.f;
        float b10 = (k1     < K) ? W[(size_t)k1       * 128 + n1] : 0.f;
        float b11 = (k1 + 1 < K) ? W[(size_t)(k1 + 1) * 128 + n1] : 0.f;
        Wp[f] = make_uint4(pack2(a00, a01), pack2(a10, a11), pack2(b00, b01), pack2(b10, b11));
    }
}

// acc + bias -> tanh -> fp16 into slab D at column base cb
template<bool ACCURATE>
__device__ __forceinline__ void epi_half(__half* __restrict__ D, const float acc[8][4],
                                         const float* __restrict__ bias, int cb, int lane){
    const int g = lane >> 2, t = lane & 3;
    #pragma unroll
    for (int l = 0; l < 8; l++){
        int col = cb + l * 8 + 2 * t;
        float b0 = bias[col], b1 = bias[col + 1];
        float y0, y1, y2, y3;
        if (ACCURATE){
            y0 = tanh_acc(acc[l][0] + b0); y1 = tanh_acc(acc[l][1] + b1);
            y2 = tanh_acc(acc[l][2] + b0); y3 = tanh_acc(acc[l][3] + b1);
        } else {
            y0 = fast_tanh(acc[l][0] + b0); y1 = fast_tanh(acc[l][1] + b1);
            y2 = fast_tanh(acc[l][2] + b0); y3 = fast_tanh(acc[l][3] + b1);
        }
        *(__half2*)(D + g * XS + col)       = __floats2half2_rn(y0, y1);
        *(__half2*)(D + (g + 8) * XS + col) = __floats2half2_rn(y2, y3);
    }
}

// attention weights from e slab: wA = w8[g] (batch A), wB = w8[8+g] (batch B)
__device__ __forceinline__ void attn_w(const __half* __restrict__ A_, int lane,
                                       float& wA, float& wB){
    float q0[4] = {0,0,0,0}, q1[4] = {0,0,0,0};
    #pragma unroll
    for (int r = 0; r < 8; r++){
        uint2 u = *(const uint2*)(A_ + r * XS + lane * 4);
        float2 f0 = __half22float2(*(__half2*)&u.x), f1 = __half22float2(*(__half2*)&u.y);
        q0[0]+=f0.x; q0[1]+=f0.y; q0[2]+=f1.x; q0[3]+=f1.y;
        uint2 v = *(const uint2*)(A_ + (r + 8) * XS + lane * 4);
        float2 g0 = __half22float2(*(__half2*)&v.x), g1 = __half22float2(*(__half2*)&v.y);
        q1[0]+=g0.x; q1[1]+=g0.y; q1[2]+=g1.x; q1[3]+=g1.y;
    }
    const float qs = 0.011048543456039806f;   // 1/(8*sqrt(128))
    #pragma unroll
    for (int j = 0; j < 4; j++){ q0[j] *= qs; q1[j] *= qs; }
    float p[16];
    #pragma unroll
    for (int r = 0; r < 16; r++){
        uint2 u = *(const uint2*)(A_ + r * XS + lane * 4);
        float2 f0 = __half22float2(*(__half2*)&u.x), f1 = __half22float2(*(__half2*)&u.y);
        const float* qq = (r < 8) ? q0 : q1;
        p[r] = qq[0]*f0.x + qq[1]*f0.y + qq[2]*f1.x + qq[3]*f1.y;
    }
    #pragma unroll
    for (int o = 16; o >= 1; o >>= 1)
        #pragma unroll
        for (int r = 0; r < 16; r++) p[r] += __shfl_xor_sync(0xffffffff, p[r], o);
    float mx0 = p[0], mx1 = p[8];
    #pragma unroll
    for (int r = 1; r < 8; r++){ mx0 = fmaxf(mx0, p[r]); mx1 = fmaxf(mx1, p[8+r]); }
    float s0 = 0.f, s1 = 0.f;
    #pragma unroll
    for (int r = 0; r < 8; r++){ s0 += __expf(p[r] - mx0); s1 += __expf(p[8+r] - mx1); }
    const int g = lane >> 2;
    wA = __expf(p[g]     - mx0) / s0;
    wB = __expf(p[8 + g] - mx1) / s1;
}

// smem offsets (fused)
#define F_W1E  0
#define F_W2E  8192
#define F_W1V  40960
#define F_W2V  73728
#define F_BS   106496
#define F_BA   108544
#define F_BB   143360
#define F_SMEM 178176

// ============================================================================
// FUSED: gather -> embed MLP -> attn -> value MLP -> combine -> AA.
// 512 threads; warp pair (2s, 2s+1) shares slab s (16 rows), split by columns.
// ============================================================================
__global__ void __launch_bounds__(512, 1)
fused_ev_kernel(const float* __restrict__ obs,
                const float* __restrict__ eW1, const float* __restrict__ eb1,
                const float* __restrict__ eW2, const float* __restrict__ eb2,
                const float* __restrict__ vW1, const float* __restrict__ vb1,
                const float* __restrict__ vW2, const float* __restrict__ vb2,
                float* __restrict__ AA, int nTiles)
{
    extern __shared__ char sm[];
    uint4* W1E = (uint4*)(sm + F_W1E);
    uint4* W2E = (uint4*)(sm + F_W2E);
    uint4* W1V = (uint4*)(sm + F_W1V);
    uint4* W2V = (uint4*)(sm + F_W2V);
    float* bs  = (float*)(sm + F_BS);
    __half* BA = (__half*)(sm + F_BA);
    __half* BB = (__half*)(sm + F_BB);

    const int tid = threadIdx.x, w = tid >> 5, lane = tid & 31;
    const int s = w >> 1, c = w & 1;

    pack_w4(eW1, W1E, 2, 30, tid, 512);
    pack_w4(eW2, W2E, 8, 128, tid, 512);
    pack_w4(vW1, W1V, 8, 128, tid, 512);
    pack_w4(vW2, W2V, 8, 128, tid, 512);
    if (tid < 128){
        bs[tid] = eb1[tid]; bs[128 + tid] = eb2[tid];
        bs[256 + tid] = vb1[tid]; bs[384 + tid] = vb2[tid];
    }
    __syncthreads();

    __half* A_ = BA + s * 16 * XS;
    __half* B_ = BB + s * 16 * XS;
    const uint4* W1Ec = W1E + c * 128;
    const uint4* W2Ec = W2E + c * 128;
    const uint4* W1Vc = W1V + c * 128;
    const uint4* W2Vc = W2V + c * 128;
    const int cb = c * 64;
    const int barid = s + 1;

    for (int tile = blockIdx.x; tile < nTiles; tile += gridDim.x){
        const int row0 = tile * 128 + s * 16;

        {   // gather: lane -> row lane>>1, 8 cols at c*16 + (lane&1)*8
            int r = lane >> 1;
            int R = row0 + r;
            int j0 = c * 16 + (lane & 1) * 8;
            const float* sp = obs + (size_t)(R & (BATCHN - 1)) * OBSD;
            const float* np = obs + (size_t)(R >> 3) * OBSD + 18 + (R & 7) * 12;
            __half* dst = A_ + r * XS;
            #pragma unroll
            for (int jj = 0; jj < 8; jj++){
                int j = j0 + jj;
                float v = (j < 18) ? sp[j] : ((j < 30) ? np[j - 18] : 0.f);
                dst[j] = __float2half_rn(v);
            }
        }
        BARS(barid);

        float acc[8][4];
        mma_half<2>(A_, W1Ec, acc, lane);              // embed L1 (K=32)
        epi_half<false>(B_, acc, bs, cb, lane);        // H -> B
        BARS(barid);
        mma_half<8>(B_, W2Ec, acc, lane);              // embed L2
        epi_half<false>(A_, acc, bs + 128, cb, lane);  // e -> A
        BARS(barid);

        float wA, wB;
        attn_w(A_, lane, wA, wB);                      // softmax weights from e

        mma_half<8>(A_, W1Vc, acc, lane);              // value L1 (reads e)
        epi_half<false>(B_, acc, bs + 256, cb, lane);  // H2 -> B
        BARS(barid);
        mma_half<8>(B_, W2Vc, acc, lane);              // value L2

        {   // v = tanh_acc(acc + b2); weighted sum over neighbors -> AA
            const int t = lane & 3;
            float* outA = AA + (size_t)(row0 >> 3) * 128;
            float* outB = outA + 128;
            #pragma unroll
            for (int l = 0; l < 8; l++){
                int col = cb + l * 8 + 2 * t;
                float b0 = bs[384 + col], b1 = bs[384 + col + 1];
                float a0 = tanh_acc(acc[l][0] + b0) * wA;
                float a1 = tanh_acc(acc[l][1] + b1) * wA;
                float e0 = tanh_acc(acc[l][2] + b0) * wB;
                float e1 = tanh_acc(acc[l][3] + b1) * wB;
                #pragma unroll
                for (int o = 4; o <= 16; o <<= 1){
                    a0 += __shfl_xor_sync(0xffffffff, a0, o);
                    a1 += __shfl_xor_sync(0xffffffff, a1, o);
                    e0 += __shfl_xor_sync(0xffffffff, e0, o);
                    e1 += __shfl_xor_sync(0xffffffff, e1, o);
                }
                if (lane < 4)      *(float2*)(outA + cb + l * 8 + lane * 2)        = make_float2(a0, a1);
                else if (lane < 8) *(float2*)(outB + cb + l * 8 + (lane & 3) * 2)  = make_float2(e0, e1);
            }
        }
    }
}

// smem offsets (agent)
#define A_W1   0
#define A_W2   32768
#define A_BS   65536
#define A_BA   66560
#define A_BB   101376
#define A_SMEM 136192

// ============================================================================
// Agent MLP: AA (fp32) -> tanh(128->128) -> tanh(128->128) -> g_av (fp16)
// ============================================================================
__global__ void __launch_bounds__(512, 1)
agent_kernel(const float* __restrict__ X,
             const float* __restrict__ W1, const float* __restrict__ b1,
             const float* __restrict__ W2, const float* __restrict__ b2,
             __half* __restrict__ Y, int nTiles)
{
    extern __shared__ char sm[];
    uint4* Wp1 = (uint4*)(sm + A_W1);
    uint4* Wp2 = (uint4*)(sm + A_W2);
    float* bs  = (float*)(sm + A_BS);
    __half* BA = (__half*)(sm + A_BA);
    __half* BB = (__half*)(sm + A_BB);

    const int tid = threadIdx.x, w = tid >> 5, lane = tid & 31;
    const int s = w >> 1, c = w & 1;

    pack_w4(W1, Wp1, 8, 128, tid, 512);
    pack_w4(W2, Wp2, 8, 128, tid, 512);
    if (tid < 128){ bs[tid] = b1[tid]; bs[128 + tid] = b2[tid]; }
    __syncthreads();

    __half* A_ = BA + s * 16 * XS;
    __half* B_ = BB + s * 16 * XS;
    const uint4* W1c = Wp1 + c * 128;
    const uint4* W2c = Wp2 + c * 128;
    const int cb = c * 64;
    const int barid = s + 1;

    for (int tile = blockIdx.x; tile < nTiles; tile += gridDim.x){
        const int row0 = tile * 128 + s * 16;
        {   // load 16x64 half-slab: lane -> row lane>>1, 8 float4s
            int r = lane >> 1, q = lane & 1;
            const float4* src = (const float4*)(X + (size_t)(row0 + r) * 128);
            __half* dst = A_ + r * XS;
            #pragma unroll
            for (int i = 0; i < 8; i++){
                int f4 = c * 16 + q * 8 + i;
                float4 u = src[f4];
                *(__half2*)(dst + f4 * 4)     = __floats2half2_rn(u.x, u.y);
                *(__half2*)(dst + f4 * 4 + 2) = __floats2half2_rn(u.z, u.w);
            }
        }
        BARS(barid);
        float acc[8][4];
        mma_half<8>(A_, W1c, acc, lane);
        epi_half<false>(B_, acc, bs, cb, lane);
        BARS(barid);
        mma_half<8>(B_, W2c, acc, lane);
        {   // output fp16 with accurate tanh
            const int g = lane >> 2, t = lane & 3;
            __half* y0 = Y + (size_t)(row0 + g) * 128;
            __half* y1 = Y + (size_t)(row0 + g + 8) * 128;
            #pragma unroll
            for (int l = 0; l < 8; l++){
                int col = cb + l * 8 + 2 * t;
                float b0 = bs[128 + col], b1 = bs[128 + col + 1];
                *(__half2*)(y0 + col) = __floats2half2_rn(tanh_acc(acc[l][0] + b0),
                                                          tanh_acc(acc[l][1] + b1));
                *(__half2*)(y1 + col) = __floats2half2_rn(tanh_acc(acc[l][2] + b0),
                                                          tanh_acc(acc[l][3] + b1));
            }
        }
    }
}

// ============================================================================
// Per-group multi-head attention (8 heads x 16 dims over 8 agents) + tile x8.
// ============================================================================
__global__ void __launch_bounds__(128)
mha_kernel(const float* __restrict__ AA, const __half* __restrict__ AV,
           float* __restrict__ out)
{
    __shared__ float ks[8][128];
    __shared__ float vs[8][128];
    const int g = blockIdx.x;
    const int j = threadIdx.x;
    const size_t base = (size_t)g * 8 * 128;

    #pragma unroll
    for (int a = 0; a < 8; a++){
        ks[a][j] = AA[base + a * 128 + j];
        vs[a][j] = __half2float(AV[base + a * 128 + j]);
    }
    __syncthreads();

    float q = 0.0f;
    #pragma unroll
    for (int a = 0; a < 8; a++) q += ks[a][j];
    q *= 0.03125f;                            // mean(1/8) * rsqrt(16)

    float s[8];
    #pragma unroll
    for (int a = 0; a < 8; a++){
        float p = q * ks[a][j];
        p += __shfl_xor_sync(0xffffffff, p, 8);
        p += __shfl_xor_sync(0xffffffff, p, 4);
        p += __shfl_xor_sync(0xffffffff, p, 2);
        p += __shfl_xor_sync(0xffffffff, p, 1);
        s[a] = p;
    }
    float mx = s[0];
    #pragma unroll
    for (int a = 1; a < 8; a++) mx = fmaxf(mx, s[a]);
    float wv[8], wsum = 0.0f;
    #pragma unroll
    for (int a = 0; a < 8; a++){ wv[a] = __expf(s[a] - mx); wsum += wv[a]; }
    const float inv = 1.0f / wsum;

    float o = 0.0f;
    #pragma unroll
    for (int a = 0; a < 8; a++) o += wv[a] * vs[a][j];
    o *= inv;

    #pragma unroll
    for (int t = 0; t < 8; t++)
        out[((size_t)(t * NGRP + g)) * 128 + j] = o;
}

// ============================================================================
extern "C" void kernel_launch(void* const* d_in, const int* in_sizes, int n_in,
                              void* d_out, int out_size)
{
    const float* obs = (const float*)d_in[0];
    const float* eW1 = (const float*)d_in[1];
    const float* eb1 = (const float*)d_in[2];
    const float* eW2 = (const float*)d_in[3];
    const float* eb2 = (const float*)d_in[4];
    const float* vW1 = (const float*)d_in[5];
    const float* vb1 = (const float*)d_in[6];
    const float* vW2 = (const float*)d_in[7];
    const float* vb2 = (const float*)d_in[8];
    const float* aW1 = (const float*)d_in[9];
    const float* ab1 = (const float*)d_in[10];
    const float* aW2 = (const float*)d_in[11];
    const float* ab2 = (const float*)d_in[12];

    float* out = (float*)d_out;                 // multi_head_attention
    float* AA  = out + (size_t)BATCHN * 128;    // agent_attention

    void* pav; cudaGetSymbolAddress(&pav, g_av);
    __half* av_g = (__half*)pav;

    cudaFuncSetAttribute(fused_ev_kernel, cudaFuncAttributeMaxDynamicSharedMemorySize, F_SMEM);
    cudaFuncSetAttribute(agent_kernel,    cudaFuncAttributeMaxDynamicSharedMemorySize, A_SMEM);

    fused_ev_kernel<<<148, 512, F_SMEM>>>(obs, eW1, eb1, eW2, eb2,
                                          vW1, vb1, vW2, vb2, AA, NROWS / 128);
    agent_kernel<<<148, 512, A_SMEM>>>(AA, aW1, ab1, aW2, ab2, av_g, BATCHN / 128);
    mha_kernel<<<NGRP, 128>>>(AA, av_g, out);
}

// round 8
// speedup vs baseline: 6.7595x; 1.0051x over previous
#include <cuda_runtime.h>
#include <cuda_fp16.h>
#include <stdint.h>

#define BATCHN 65536
#define NROWS  (BATCHN * 8)
#define NGRP   8192
#define OBSD   114
#define XS     136   // slab stride in halves (272B rows -> conflict-free A frags)

__device__ __half g_av[(size_t)BATCHN * 128];   // agent values, fp16 (16 MB)

__device__ __forceinline__ float fast_tanh(float x){float y;asm("tanh.approx.f32 %0,%1;":"=f"(y):"f"(x));return y;}
__device__ __forceinline__ float tanh_acc(float x){ return 1.f - __fdividef(2.f, __expf(2.f * x) + 1.f); }
__device__ __forceinline__ uint32_t pack2(float a, float b){ __half2 h = __floats2half2_rn(a, b); return *(uint32_t*)&h; }

#define BARS(id) asm volatile("bar.sync %0, 128;" :: "r"(id) : "memory")

__device__ __forceinline__ void mma16(float c[4], uint32_t a0, uint32_t a1, uint32_t a2, uint32_t a3,
                                      uint32_t b0, uint32_t b1){
    asm volatile("mma.sync.aligned.m16n8k16.row.col.f32.f16.f16.f32 "
                 "{%0,%1,%2,%3},{%4,%5,%6,%7},{%8,%9},{%0,%1,%2,%3};"
                 : "+f"(c[0]), "+f"(c[1]), "+f"(c[2]), "+f"(c[3])
                 : "r"(a0), "r"(a1), "r"(a2), "r"(a3), "r"(b0), "r"(b1));
}

// Warp computes 64 rows x 32 cols (quarter c). acc[l=rt*4+j][4].
// Wc = Wp + (2c)*32. Wp layout: [(ks*8+ntp)*32+lane] = uint4{2 n-tile frag pairs}.
template<int KS>
__device__ __forceinline__ void mma64(const __half* __restrict__ Xh,
                                      const uint4* __restrict__ Wc,
                                      float acc[16][4], int lane){
    const int g = lane >> 2, t = lane & 3;
    #pragma unroll
    for (int l = 0; l < 16; l++){ acc[l][0]=acc[l][1]=acc[l][2]=acc[l][3]=0.f; }
    #pragma unroll
    for (int ks = 0; ks < KS; ks++){
        uint4 bA = Wc[ks * 256 + lane];
        uint4 bB = Wc[ks * 256 + 32 + lane];
        #pragma unroll
        for (int rt = 0; rt < 4; rt++){
            const __half* ab = Xh + (rt * 16 + g) * XS + ks * 16 + 2 * t;
            uint32_t a0 = *(const uint32_t*)ab;
            uint32_t a1 = *(const uint32_t*)(ab + 8 * XS);
            uint32_t a2 = *(const uint32_t*)(ab + 8);
            uint32_t a3 = *(const uint32_t*)(ab + 8 * XS + 8);
            mma16(acc[rt*4+0], a0,a1,a2,a3, bA.x, bA.y);
            mma16(acc[rt*4+1], a0,a1,a2,a3, bA.z, bA.w);
            mma16(acc[rt*4+2], a0,a1,a2,a3, bB.x, bB.y);
            mma16(acc[rt*4+3], a0,a1,a2,a3, bB.z, bB.w);
        }
    }
}

// Pack W[k][n] (row-major K x 128 fp32) into uint4 B-fragment-pair order.
__device__ __forceinline__ void pack_w4(const float* __restrict__ W, uint4* __restrict__ Wp,
                                        int KS, int K, int tid, int nthr){
    for (int f = tid; f < KS * 8 * 32; f += nthr){
        int ks = f >> 8, ntp = (f >> 5) & 7, lane = f & 31;
        int g = lane >> 2, t = lane & 3;
        int n0 = ntp * 16 + g, n1 = n0 + 8;
        int k0 = ks * 16 + 2 * t, k1 = k0 + 8;
        float a00 = (k0     < K) ? W[(size_t)k0       * 128 + n0] : 0.f;
        float a01 = (k0 + 1 < K) ? W[(size_t)(k0 + 1) * 128 + n0] : 0.f;
        float a10 = (k1     < K) ? W[(size_t)k1       * 128 + n0] : 0.f;
        float a11 = (k1 + 1 < K) ? W[(size_t)(k1 + 1) * 128 + n0] : 0.f;
        float b00 = (k0     < K) ? W[(size_t)k0       * 128 + n1] : 0.f;
        float b01 = (k0 + 1 < K) ? W[(size_t)(k0 + 1) * 128 + n1] : 0.f;
        float b10 = (k1     < K) ? W[(size_t)k1       * 128 + n1] : 0.f;
        float b11 = (k1 + 1 < K) ? W[(size_t)(k1 + 1) * 128 + n1] : 0.f;
        Wp[f] = make_uint4(pack2(a00, a01), pack2(a10, a11), pack2(b00, b01), pack2(b10, b11));
    }
}

// acc + bias -> fast tanh -> fp16 slab D (warp's 64 rows x 32 cols at col base cb)
__device__ __forceinline__ void epi64(__half* __restrict__ D, const float acc[16][4],
                                      const float* __restrict__ bias, int cb, int lane){
    const int g = lane >> 2, t = lane & 3;
    #pragma unroll
    for (int l = 0; l < 16; l++){
        int rt = l >> 2, j = l & 3;
        int col = cb + j * 8 + 2 * t;
        float b0 = bias[col], b1 = bias[col + 1];
        *(__half2*)(D + (rt*16 + g) * XS + col) =
            __floats2half2_rn(fast_tanh(acc[l][0] + b0), fast_tanh(acc[l][1] + b1));
        *(__half2*)(D + (rt*16 + g + 8) * XS + col) =
            __floats2half2_rn(fast_tanh(acc[l][2] + b0), fast_tanh(acc[l][3] + b1));
    }
}

// attention weights for 2 batches (16 rows at E16 = e slab + c*16*XS); writes
// per-row weights to w8row[0..15] (w8row = w8s + s*64 + c*16).
__device__ __forceinline__ void attn_w16(const __half* __restrict__ E16,
                                         float* __restrict__ w8row, int lane){
    float q0[4] = {0,0,0,0}, q1[4] = {0,0,0,0};
    #pragma unroll
    for (int r = 0; r < 8; r++){
        uint2 u = *(const uint2*)(E16 + r * XS + lane * 4);
        float2 f0 = __half22float2(*(__half2*)&u.x), f1 = __half22float2(*(__half2*)&u.y);
        q0[0]+=f0.x; q0[1]+=f0.y; q0[2]+=f1.x; q0[3]+=f1.y;
        uint2 v = *(const uint2*)(E16 + (r + 8) * XS + lane * 4);
        float2 g0 = __half22float2(*(__half2*)&v.x), g1 = __half22float2(*(__half2*)&v.y);
        q1[0]+=g0.x; q1[1]+=g0.y; q1[2]+=g1.x; q1[3]+=g1.y;
    }
    const float qs = 0.011048543456039806f;   // 1/(8*sqrt(128))
    #pragma unroll
    for (int j = 0; j < 4; j++){ q0[j] *= qs; q1[j] *= qs; }
    float p[16];
    #pragma unroll
    for (int r = 0; r < 16; r++){
        uint2 u = *(const uint2*)(E16 + r * XS + lane * 4);
        float2 f0 = __half22float2(*(__half2*)&u.x), f1 = __half22float2(*(__half2*)&u.y);
        const float* qq = (r < 8) ? q0 : q1;
        p[r] = qq[0]*f0.x + qq[1]*f0.y + qq[2]*f1.x + qq[3]*f1.y;
    }
    #pragma unroll
    for (int o = 16; o >= 1; o >>= 1)
        #pragma unroll
        for (int r = 0; r < 16; r++) p[r] += __shfl_xor_sync(0xffffffff, p[r], o);
    float mx0 = p[0], mx1 = p[8];
    #pragma unroll
    for (int r = 1; r < 8; r++){ mx0 = fmaxf(mx0, p[r]); mx1 = fmaxf(mx1, p[8+r]); }
    float s0 = 0.f, s1 = 0.f;
    #pragma unroll
    for (int r = 0; r < 8; r++){ s0 += __expf(p[r] - mx0); s1 += __expf(p[8+r] - mx1); }
    const int g = lane >> 2, t = lane & 3;
    float wA = __expf(p[g]     - mx0) / s0;     // weight of neighbor g, batch A
    float wB = __expf(p[8 + g] - mx1) / s1;     // weight of neighbor g, batch B
    if (t == 0){ w8row[g] = wA; w8row[8 + g] = wB; }
}

// smem offsets (fused)
#define F_W1E  0
#define F_W2E  8192
#define F_W1V  40960
#define F_W2V  73728
#define F_BS   106496
#define F_W8   108544
#define F_BA   109568
#define F_BB   161792
#define F_SMEM 214016

// ============================================================================
// FUSED: gather -> embed MLP -> attn -> value MLP -> combine -> AA.
// 384 threads; quad s (4 warps) owns 64-row slab, warp c = col quarter.
// ============================================================================
__global__ void __launch_bounds__(384, 1)
fused_ev_kernel(const float* __restrict__ obs,
                const float* __restrict__ eW1, const float* __restrict__ eb1,
                const float* __restrict__ eW2, const float* __restrict__ eb2,
                const float* __restrict__ vW1, const float* __restrict__ vb1,
                const float* __restrict__ vW2, const float* __restrict__ vb2,
                float* __restrict__ AA, int nTiles)
{
    extern __shared__ char sm[];
    uint4* W1E = (uint4*)(sm + F_W1E);
    uint4* W2E = (uint4*)(sm + F_W2E);
    uint4* W1V = (uint4*)(sm + F_W1V);
    uint4* W2V = (uint4*)(sm + F_W2V);
    float* bs  = (float*)(sm + F_BS);
    float* w8s = (float*)(sm + F_W8);
    __half* BA = (__half*)(sm + F_BA);
    __half* BB = (__half*)(sm + F_BB);

    const int tid = threadIdx.x, w = tid >> 5, lane = tid & 31;
    const int s = w >> 2, c = w & 3;

    pack_w4(eW1, W1E, 2, 30, tid, 384);
    pack_w4(eW2, W2E, 8, 128, tid, 384);
    pack_w4(vW1, W1V, 8, 128, tid, 384);
    pack_w4(vW2, W2V, 8, 128, tid, 384);
    if (tid < 128){
        bs[tid] = eb1[tid]; bs[128 + tid] = eb2[tid];
        bs[256 + tid] = vb1[tid]; bs[384 + tid] = vb2[tid];
    }
    __syncthreads();

    __half* A_ = BA + s * 64 * XS;
    __half* B_ = BB + s * 64 * XS;
    float* w8sl = w8s + s * 64;
    const uint4* W1Ec = W1E + (2 * c) * 32;
    const uint4* W2Ec = W2E + (2 * c) * 32;
    const uint4* W1Vc = W1V + (2 * c) * 32;
    const uint4* W2Vc = W2V + (2 * c) * 32;
    const int cb = c * 32;
    const int barid = s + 1;
    const int qtid = c * 32 + lane;           // 0..127 within quad
    const int g = lane >> 2, t = lane & 3;

    for (int tile = blockIdx.x; tile < nTiles; tile += gridDim.x){
        const int row0 = tile * 192 + s * 64;
        if (row0 >= NROWS) continue;          // uniform per quad (slab granularity)

        {   // gather 64 rows x 32 cols: 2 threads/row, 16 cols each
            int r = qtid >> 1, j0 = (qtid & 1) * 16;
            int R = row0 + r;
            const float* sp = obs + (size_t)(R & (BATCHN - 1)) * OBSD;
            const float* np = obs + (size_t)(R >> 3) * OBSD + 18 + (R & 7) * 12;
            __half* dst = A_ + r * XS;
            #pragma unroll
            for (int jj = 0; jj < 16; jj++){
                int j = j0 + jj;
                float v = (j < 18) ? sp[j] : ((j < 30) ? np[j - 18] : 0.f);
                dst[j] = __float2half_rn(v);
            }
        }
        BARS(barid);

        float acc[16][4];
        mma64<2>(A_, W1Ec, acc, lane);            // embed L1 (K=32)
        epi64(B_, acc, bs, cb, lane);             // H -> B
        BARS(barid);
        mma64<8>(B_, W2Ec, acc, lane);            // embed L2
        epi64(A_, acc, bs + 128, cb, lane);       // e -> A
        BARS(barid);

        attn_w16(A_ + c * 16 * XS, w8sl + c * 16, lane);   // warp c: batches 2c, 2c+1

        mma64<8>(A_, W1Vc, acc, lane);            // value L1 (reads e)
        epi64(B_, acc, bs + 256, cb, lane);       // H2 -> B
        BARS(barid);                              // also publishes w8s
        mma64<8>(B_, W2Vc, acc, lane);            // value L2

        {   // v = tanh_acc(acc+b2); weighted neighbor sum -> AA
            #pragma unroll
            for (int rt = 0; rt < 4; rt++){
                const float wa = w8sl[rt * 16 + g];       // rows rt*16+g  (batch 2rt)
                const float wb = w8sl[rt * 16 + 8 + g];   // rows rt*16+8+g (batch 2rt+1)
                float* outA = AA + (size_t)(tile * 24 + s * 8 + 2 * rt) * 128;
                float* outB = outA + 128;
                #pragma unroll
                for (int j = 0; j < 4; j++){
                    int l = rt * 4 + j;
                    int col = cb + j * 8 + 2 * t;
                    float b0 = bs[384 + col], b1 = bs[384 + col + 1];
                    float a0 = tanh_acc(acc[l][0] + b0) * wa;
                    float a1 = tanh_acc(acc[l][1] + b1) * wa;
                    float e0 = tanh_acc(acc[l][2] + b0) * wb;
                    float e1 = tanh_acc(acc[l][3] + b1) * wb;
                    #pragma unroll
                    for (int o = 4; o <= 16; o <<= 1){
                        a0 += __shfl_xor_sync(0xffffffff, a0, o);
                        a1 += __shfl_xor_sync(0xffffffff, a1, o);
                        e0 += __shfl_xor_sync(0xffffffff, e0, o);
                        e1 += __shfl_xor_sync(0xffffffff, e1, o);
                    }
                    if (lane < 4)      *(float2*)(outA + cb + j * 8 + lane * 2)       = make_float2(a0, a1);
                    else if (lane < 8) *(float2*)(outB + cb + j * 8 + (lane & 3) * 2) = make_float2(e0, e1);
                }
            }
        }
    }
}

// smem offsets (agent)
#define A_W1   0
#define A_W2   32768
#define A_BS   65536
#define A_BA   66560
#define A_BB   118784
#define A_SMEM 171008

// ============================================================================
// Agent MLP: AA (fp32) -> tanh(128->128) -> tanh(128->128) -> g_av (fp16)
// ============================================================================
__global__ void __launch_bounds__(384, 1)
agent_kernel(const float* __restrict__ X,
             const float* __restrict__ W1, const float* __restrict__ b1,
             const float* __restrict__ W2, const float* __restrict__ b2,
             __half* __restrict__ Y, int nTiles)
{
    extern __shared__ char sm[];
    uint4* Wp1 = (uint4*)(sm + A_W1);
    uint4* Wp2 = (uint4*)(sm + A_W2);
    float* bs  = (float*)(sm + A_BS);
    __half* BA = (__half*)(sm + A_BA);
    __half* BB = (__half*)(sm + A_BB);

    const int tid = threadIdx.x, w = tid >> 5, lane = tid & 31;
    const int s = w >> 2, c = w & 3;

    pack_w4(W1, Wp1, 8, 128, tid, 384);
    pack_w4(W2, Wp2, 8, 128, tid, 384);
    if (tid < 128){ bs[tid] = b1[tid]; bs[128 + tid] = b2[tid]; }
    __syncthreads();

    __half* A_ = BA + s * 64 * XS;
    __half* B_ = BB + s * 64 * XS;
    const uint4* W1c = Wp1 + (2 * c) * 32;
    const uint4* W2c = Wp2 + (2 * c) * 32;
    const int cb = c * 32;
    const int barid = s + 1;
    const int qtid = c * 32 + lane;
    const int g = lane >> 2, t = lane & 3;

    for (int tile = blockIdx.x; tile < nTiles; tile += gridDim.x){
        const int row0 = tile * 192 + s * 64;
        if (row0 >= BATCHN) continue;

        {   // load 64x128 slab fp32 -> fp16: 2 threads/row, 16 float4 each
            int r = qtid >> 1, hh = qtid & 1;
            const float4* src = (const float4*)(X + (size_t)(row0 + r) * 128);
            __half* dst = A_ + r * XS;
            #pragma unroll
            for (int i = 0; i < 16; i++){
                int f4 = hh * 16 + i;
                float4 u = src[f4];
                *(__half2*)(dst + f4 * 4)     = __floats2half2_rn(u.x, u.y);
                *(__half2*)(dst + f4 * 4 + 2) = __floats2half2_rn(u.z, u.w);
            }
        }
        BARS(barid);
        float acc[16][4];
        mma64<8>(A_, W1c, acc, lane);
        epi64(B_, acc, bs, cb, lane);
        BARS(barid);
        mma64<8>(B_, W2c, acc, lane);
        {   // output fp16 with accurate tanh
            #pragma unroll
            for (int l = 0; l < 16; l++){
                int rt = l >> 2, j = l & 3;
                int col = cb + j * 8 + 2 * t;
                float b0 = bs[128 + col], b1 = bs[128 + col + 1];
                __half* y0 = Y + (size_t)(row0 + rt*16 + g) * 128;
                __half* y1 = Y + (size_t)(row0 + rt*16 + g + 8) * 128;
                *(__half2*)(y0 + col) = __floats2half2_rn(tanh_acc(acc[l][0] + b0),
                                                          tanh_acc(acc[l][1] + b1));
                *(__half2*)(y1 + col) = __floats2half2_rn(tanh_acc(acc[l][2] + b0),
                                                          tanh_acc(acc[l][3] + b1));
            }
        }
    }
}

// ============================================================================
// Per-group multi-head attention (8 heads x 16 dims over 8 agents) + tile x8.
// ============================================================================
__global__ void __launch_bounds__(128)
mha_kernel(const float* __restrict__ AA, const __half* __restrict__ AV,
           float* __restrict__ out)
{
    __shared__ float ks[8][128];
    __shared__ float vs[8][128];
    const int g = blockIdx.x;
    const int j = threadIdx.x;
    const size_t base = (size_t)g * 8 * 128;

    #pragma unroll
    for (int a = 0; a < 8; a++){
        ks[a][j] = AA[base + a * 128 + j];
        vs[a][j] = __half2float(AV[base + a * 128 + j]);
    }
    __syncthreads();

    float q = 0.0f;
    #pragma unroll
    for (int a = 0; a < 8; a++) q += ks[a][j];
    q *= 0.03125f;                            // mean(1/8) * rsqrt(16)

    float s[8];
    #pragma unroll
    for (int a = 0; a < 8; a++){
        float p = q * ks[a][j];
        p += __shfl_xor_sync(0xffffffff, p, 8);
        p += __shfl_xor_sync(0xffffffff, p, 4);
        p += __shfl_xor_sync(0xffffffff, p, 2);
        p += __shfl_xor_sync(0xffffffff, p, 1);
        s[a] = p;
    }
    float mx = s[0];
    #pragma unroll
    for (int a = 1; a < 8; a++) mx = fmaxf(mx, s[a]);
    float wv[8], wsum = 0.0f;
    #pragma unroll
    for (int a = 0; a < 8; a++){ wv[a] = __expf(s[a] - mx); wsum += wv[a]; }
    const float inv = 1.0f / wsum;

    float o = 0.0f;
    #pragma unroll
    for (int a = 0; a < 8; a++) o += wv[a] * vs[a][j];
    o *= inv;

    #pragma unroll
    for (int t = 0; t < 8; t++)
        out[((size_t)(t * NGRP + g)) * 128 + j] = o;
}

// ============================================================================
extern "C" void kernel_launch(void* const* d_in, const int* in_sizes, int n_in,
                              void* d_out, int out_size)
{
    const float* obs = (const float*)d_in[0];
    const float* eW1 = (const float*)d_in[1];
    const float* eb1 = (const float*)d_in[2];
    const float* eW2 = (const float*)d_in[3];
    const float* eb2 = (const float*)d_in[4];
    const float* vW1 = (const float*)d_in[5];
    const float* vb1 = (const float*)d_in[6];
    const float* vW2 = (const float*)d_in[7];
    const float* vb2 = (const float*)d_in[8];
    const float* aW1 = (const float*)d_in[9];
    const float* ab1 = (const float*)d_in[10];
    const float* aW2 = (const float*)d_in[11];
    const float* ab2 = (const float*)d_in[12];

    float* out = (float*)d_out;                 // multi_head_attention
    float* AA  = out + (size_t)BATCHN * 128;    // agent_attention

    void* pav; cudaGetSymbolAddress(&pav, g_av);
    __half* av_g = (__half*)pav;

    cudaFuncSetAttribute(fused_ev_kernel, cudaFuncAttributeMaxDynamicSharedMemorySize, F_SMEM);
    cudaFuncSetAttribute(agent_kernel,    cudaFuncAttributeMaxDynamicSharedMemorySize, A_SMEM);

    const int nTilesF = (NROWS  + 191) / 192;   // 2731
    const int nTilesA = (BATCHN + 191) / 192;   // 342

    fused_ev_kernel<<<148, 384, F_SMEM>>>(obs, eW1, eb1, eW2, eb2,
                                          vW1, vb1, vW2, vb2, AA, nTilesF);
    agent_kernel<<<148, 384, A_SMEM>>>(AA, aW1, ab1, aW2, ab2, av_g, nTilesA);
    mha_kernel<<<NGRP, 128>>>(AA, av_g, out);
}

// round 9
// speedup vs baseline: 7.5817x; 1.1216x over previous
#include <cuda_runtime.h>
#include <cuda_fp16.h>
#include <stdint.h>

#define BATCHN 65536
#define NROWS  (BATCHN * 8)
#define NGRP   8192
#define OBSD   114

__device__ __half g_av[(size_t)BATCHN * 128];   // agent values, fp16 (16 MB)

__device__ __forceinline__ float fast_tanh(float x){float y;asm("tanh.approx.f32 %0,%1;":"=f"(y):"f"(x));return y;}
__device__ __forceinline__ float tanh_acc(float x){ return 1.f - __fdividef(2.f, __expf(2.f * x) + 1.f); }
__device__ __forceinline__ uint32_t pack2(float a, float b){ __half2 h = __floats2half2_rn(a, b); return *(uint32_t*)&h; }

__device__ __forceinline__ void mma16(float c[4], uint32_t a0, uint32_t a1, uint32_t a2, uint32_t a3,
                                      uint32_t b0, uint32_t b1){
    asm volatile("mma.sync.aligned.m16n8k16.row.col.f32.f16.f16.f32 "
                 "{%0,%1,%2,%3},{%4,%5,%6,%7},{%8,%9},{%0,%1,%2,%3};"
                 : "+f"(c[0]), "+f"(c[1]), "+f"(c[2]), "+f"(c[3])
                 : "r"(a0), "r"(a1), "r"(a2), "r"(a3), "r"(b0), "r"(b1));
}

// Full-width layer: warp's 16 rows x 128 cols. A-fragments af[ks][4] in regs.
// Wp layout: [(ks*8+ntp)*32+lane] = uint4{frags for nt=2ntp, 2ntp+1}.
template<int KS>
__device__ __forceinline__ void mma_reg(const uint32_t af[][4], const uint4* __restrict__ Wp,
                                        float acc[16][4], int lane){
    #pragma unroll
    for (int nt = 0; nt < 16; nt++){ acc[nt][0]=acc[nt][1]=acc[nt][2]=acc[nt][3]=0.f; }
    #pragma unroll
    for (int ks = 0; ks < KS; ks++){
        #pragma unroll
        for (int ntp = 0; ntp < 8; ntp++){
            uint4 b = Wp[ks * 256 + ntp * 32 + lane];
            mma16(acc[2*ntp],   af[ks][0], af[ks][1], af[ks][2], af[ks][3], b.x, b.y);
            mma16(acc[2*ntp+1], af[ks][0], af[ks][1], af[ks][2], af[ks][3], b.z, b.w);
        }
    }
}

// acc(+bias) -> fast tanh -> repack as next layer's A-fragments (in registers).
// D frag (nt, d0..d3) == A frag (ks=nt/2): af[ks][0]=(g,klo) af[ks][1]=(g+8,klo)
// af[ks][2]=(g,khi) af[ks][3]=(g+8,khi).
__device__ __forceinline__ void transition(const float acc[16][4], uint32_t af[8][4],
                                           const float* __restrict__ bias, int t){
    #pragma unroll
    for (int ks = 0; ks < 8; ks++){
        int c0 = (2*ks) * 8 + 2 * t, c1 = c0 + 8;
        float b00 = bias[c0], b01 = bias[c0 + 1];
        float b10 = bias[c1], b11 = bias[c1 + 1];
        af[ks][0] = pack2(fast_tanh(acc[2*ks][0] + b00),   fast_tanh(acc[2*ks][1] + b01));
        af[ks][1] = pack2(fast_tanh(acc[2*ks][2] + b00),   fast_tanh(acc[2*ks][3] + b01));
        af[ks][2] = pack2(fast_tanh(acc[2*ks+1][0] + b10), fast_tanh(acc[2*ks+1][1] + b11));
        af[ks][3] = pack2(fast_tanh(acc[2*ks+1][2] + b10), fast_tanh(acc[2*ks+1][3] + b11));
    }
}

// Pack W[k][n] (row-major K x 128 fp32) into uint4 B-fragment-pair order.
__device__ __forceinline__ void pack_w4(const float* __restrict__ W, uint4* __restrict__ Wp,
                                        int KS, int K, int tid, int nthr){
    for (int f = tid; f < KS * 8 * 32; f += nthr){
        int ks = f >> 8, ntp = (f >> 5) & 7, lane = f & 31;
        int g = lane >> 2, t = lane & 3;
        int n0 = ntp * 16 + g, n1 = n0 + 8;
        int k0 = ks * 16 + 2 * t, k1 = k0 + 8;
        float a00 = (k0     < K) ? W[(size_t)k0       * 128 + n0] : 0.f;
        float a01 = (k0 + 1 < K) ? W[(size_t)(k0 + 1) * 128 + n0] : 0.f;
        float a10 = (k1     < K) ? W[(size_t)k1       * 128 + n0] : 0.f;
        float a11 = (k1 + 1 < K) ? W[(size_t)(k1 + 1) * 128 + n0] : 0.f;
        float b00 = (k0     < K) ? W[(size_t)k0       * 128 + n1] : 0.f;
        float b01 = (k0 + 1 < K) ? W[(size_t)(k0 + 1) * 128 + n1] : 0.f;
        float b10 = (k1     < K) ? W[(size_t)k1       * 128 + n1] : 0.f;
        float b11 = (k1 + 1 < K) ? W[(size_t)(k1 + 1) * 128 + n1] : 0.f;
        Wp[f] = make_uint4(pack2(a00, a01), pack2(a10, a11), pack2(b00, b01), pack2(b10, b11));
    }
}

// smem offsets (fused)
#define F_W1E  0
#define F_W2E  8192
#define F_W1V  40960
#define F_W2V  73728
#define F_BS   106496
#define F_STG  108544
#define F_SMEM 123904   // + 12 warps * 16 rows * 40 halves * 2B

// ============================================================================
// FUSED: gather -> embed MLP -> attn -> value MLP -> combine -> AA.
// Warp owns a 16-row slab (2 batches), all 128 cols; barrier-free main loop.
// lane = g*4 + t (g = row-in-8-group / neighbor id, t = k-quarter).
// ============================================================================
__global__ void __launch_bounds__(384, 1)
fused_ev_kernel(const float* __restrict__ obs,
                const float* __restrict__ eW1, const float* __restrict__ eb1,
                const float* __restrict__ eW2, const float* __restrict__ eb2,
                const float* __restrict__ vW1, const float* __restrict__ vb1,
                const float* __restrict__ vW2, const float* __restrict__ vb2,
                float* __restrict__ AA)
{
    extern __shared__ char sm[];
    uint4* W1E = (uint4*)(sm + F_W1E);
    uint4* W2E = (uint4*)(sm + F_W2E);
    uint4* W1V = (uint4*)(sm + F_W1V);
    uint4* W2V = (uint4*)(sm + F_W2V);
    float* bs  = (float*)(sm + F_BS);

    const int tid = threadIdx.x, w = tid >> 5, lane = tid & 31;
    const int g = lane >> 2, t = lane & 3;

    pack_w4(eW1, W1E, 2, 30, tid, 384);
    pack_w4(eW2, W2E, 8, 128, tid, 384);
    pack_w4(vW1, W1V, 8, 128, tid, 384);
    pack_w4(vW2, W2V, 8, 128, tid, 384);
    if (tid < 128){
        bs[tid] = eb1[tid]; bs[128 + tid] = eb2[tid];
        bs[256 + tid] = vb1[tid]; bs[384 + tid] = vb2[tid];
    }
    __syncthreads();

    __half* stg = (__half*)(sm + F_STG) + w * 16 * 40;   // 40-half rows: conflict-free frags
    const float qs = 0.011048543456039806f;              // 1/(8*sqrt(128))
    const int NSLAB = NROWS / 16;                        // 32768
    const int step  = gridDim.x * 12;

    for (int slab = blockIdx.x * 12 + w; slab < NSLAB; slab += step){
        const int row0 = slab * 16;

        {   // ---- gather 16 rows x 32 cols (cols>=30 zero) into stage ----
            int r = lane >> 1, q = lane & 1;
            int R = row0 + r;
            const float* sp = obs + (size_t)(R & (BATCHN - 1)) * OBSD;
            const float* np = obs + (size_t)(R >> 3) * OBSD + 18 + (R & 7) * 12;
            uint32_t h[8];
            #pragma unroll
            for (int jj = 0; jj < 8; jj++){
                int c = q * 16 + 2 * jj;
                float v0 = (c     < 18) ? sp[c]     : ((c     < 30) ? np[c - 18] : 0.f);
                float v1 = (c + 1 < 18) ? sp[c + 1] : ((c + 1 < 30) ? np[c - 17] : 0.f);
                h[jj] = pack2(v0, v1);
            }
            *(uint4*)(stg + r * 40 + q * 16)     = make_uint4(h[0], h[1], h[2], h[3]);
            *(uint4*)(stg + r * 40 + q * 16 + 8) = make_uint4(h[4], h[5], h[6], h[7]);
        }
        __syncwarp();

        // ---- embed L1 (K=32): A-frags from stage ----
        uint32_t af1[2][4];
        {
            const __half* s0 = stg + g * 40;
            const __half* s1 = stg + (g + 8) * 40;
            #pragma unroll
            for (int ks = 0; ks < 2; ks++){
                af1[ks][0] = *(const uint32_t*)(s0 + ks * 16 + 2 * t);
                af1[ks][1] = *(const uint32_t*)(s1 + ks * 16 + 2 * t);
                af1[ks][2] = *(const uint32_t*)(s0 + ks * 16 + 2 * t + 8);
                af1[ks][3] = *(const uint32_t*)(s1 + ks * 16 + 2 * t + 8);
            }
        }
        float acc[16][4];
        uint32_t af[8][4];
        mma_reg<2>(af1, W1E, acc, lane);
        transition(acc, af, bs, t);            // h1 -> af
        mma_reg<8>(af, W2E, acc, lane);        // embed L2
        transition(acc, af, bs + 128, t);      // e -> af (fp16, stays in regs)

        // ---- attention weights from e (af) via g-dim shuffles ----
        float wA, wB;
        {
            float fa[32];
            // batch A (rows g): half2 regs af[ks][0], af[ks][2]
            #pragma unroll
            for (int ks = 0; ks < 8; ks++){
                float2 u0 = __half22float2(*(__half2*)&af[ks][0]);
                float2 u2 = __half22float2(*(__half2*)&af[ks][2]);
                fa[4*ks]=u0.x; fa[4*ks+1]=u0.y; fa[4*ks+2]=u2.x; fa[4*ks+3]=u2.y;
            }
            #pragma unroll
            for (int o = 4; o <= 16; o <<= 1)
                #pragma unroll
                for (int i = 0; i < 32; i++) fa[i] += __shfl_xor_sync(0xffffffff, fa[i], o);
            float sA = 0.f;
            #pragma unroll
            for (int ks = 0; ks < 8; ks++){
                float2 u0 = __half22float2(*(__half2*)&af[ks][0]);
                float2 u2 = __half22float2(*(__half2*)&af[ks][2]);
                sA += fa[4*ks]*u0.x + fa[4*ks+1]*u0.y + fa[4*ks+2]*u2.x + fa[4*ks+3]*u2.y;
            }
            sA *= qs;
            sA += __shfl_xor_sync(0xffffffff, sA, 1);
            sA += __shfl_xor_sync(0xffffffff, sA, 2);
            // batch B (rows g+8): af[ks][1], af[ks][3]
            #pragma unroll
            for (int ks = 0; ks < 8; ks++){
                float2 u1 = __half22float2(*(__half2*)&af[ks][1]);
                float2 u3 = __half22float2(*(__half2*)&af[ks][3]);
                fa[4*ks]=u1.x; fa[4*ks+1]=u1.y; fa[4*ks+2]=u3.x; fa[4*ks+3]=u3.y;
            }
            #pragma unroll
            for (int o = 4; o <= 16; o <<= 1)
                #pragma unroll
                for (int i = 0; i < 32; i++) fa[i] += __shfl_xor_sync(0xffffffff, fa[i], o);
            float sB = 0.f;
            #pragma unroll
            for (int ks = 0; ks < 8; ks++){
                float2 u1 = __half22float2(*(__half2*)&af[ks][1]);
                float2 u3 = __half22float2(*(__half2*)&af[ks][3]);
                sB += fa[4*ks]*u1.x + fa[4*ks+1]*u1.y + fa[4*ks+2]*u3.x + fa[4*ks+3]*u3.y;
            }
            sB *= qs;
            sB += __shfl_xor_sync(0xffffffff, sB, 1);
            sB += __shfl_xor_sync(0xffffffff, sB, 2);
            // softmax over g (scores sA(g), sB(g) live on g-groups)
            float mxA = sA, mxB = sB;
            #pragma unroll
            for (int o = 4; o <= 16; o <<= 1){
                mxA = fmaxf(mxA, __shfl_xor_sync(0xffffffff, mxA, o));
                mxB = fmaxf(mxB, __shfl_xor_sync(0xffffffff, mxB, o));
            }
            float eA = __expf(sA - mxA), eB = __expf(sB - mxB);
            float uA = eA, uB = eB;
            #pragma unroll
            for (int o = 4; o <= 16; o <<= 1){
                uA += __shfl_xor_sync(0xffffffff, uA, o);
                uB += __shfl_xor_sync(0xffffffff, uB, o);
            }
            wA = eA / uA; wB = eB / uB;
        }

        // ---- value MLP on e ----
        mma_reg<8>(af, W1V, acc, lane);
        transition(acc, af, bs + 256, t);      // h2 -> af
        mma_reg<8>(af, W2V, acc, lane);

        // ---- v = tanh_acc(acc+b2); weighted sum over neighbors (g-dim) -> AA ----
        #pragma unroll
        for (int nt = 0; nt < 16; nt++){
            int c = nt * 8 + 2 * t;
            float b0 = bs[384 + c], b1 = bs[384 + c + 1];
            acc[nt][0] = tanh_acc(acc[nt][0] + b0) * wA;
            acc[nt][1] = tanh_acc(acc[nt][1] + b1) * wA;
            acc[nt][2] = tanh_acc(acc[nt][2] + b0) * wB;
            acc[nt][3] = tanh_acc(acc[nt][3] + b1) * wB;
        }
        #pragma unroll
        for (int o = 4; o <= 16; o <<= 1)
            #pragma unroll
            for (int nt = 0; nt < 16; nt++){
                acc[nt][0] += __shfl_xor_sync(0xffffffff, acc[nt][0], o);
                acc[nt][1] += __shfl_xor_sync(0xffffffff, acc[nt][1], o);
                acc[nt][2] += __shfl_xor_sync(0xffffffff, acc[nt][2], o);
                acc[nt][3] += __shfl_xor_sync(0xffffffff, acc[nt][3], o);
            }
        float* outA = AA + (size_t)(slab * 2) * 128;
        if (lane < 4){
            #pragma unroll
            for (int nt = 0; nt < 16; nt++)
                *(float2*)(outA + nt * 8 + 2 * t) = make_float2(acc[nt][0], acc[nt][1]);
        } else if (lane < 8){
            #pragma unroll
            for (int nt = 0; nt < 16; nt++)
                *(float2*)(outA + 128 + nt * 8 + 2 * t) = make_float2(acc[nt][2], acc[nt][3]);
        }
    }
}

// smem offsets (agent)
#define A_W1   0
#define A_W2   32768
#define A_BS   65536
#define A_SMEM 66560

// ============================================================================
// Agent MLP: AA (fp32) -> tanh(128->128) -> tanh(128->128) -> g_av (fp16)
// Register-chained; A-frags built directly from gmem float2 loads.
// ============================================================================
__global__ void __launch_bounds__(384, 1)
agent_kernel(const float* __restrict__ X,
             const float* __restrict__ W1, const float* __restrict__ b1,
             const float* __restrict__ W2, const float* __restrict__ b2,
             __half* __restrict__ Y)
{
    extern __shared__ char sm[];
    uint4* Wp1 = (uint4*)(sm + A_W1);
    uint4* Wp2 = (uint4*)(sm + A_W2);
    float* bs  = (float*)(sm + A_BS);

    const int tid = threadIdx.x, w = tid >> 5, lane = tid & 31;
    const int g = lane >> 2, t = lane & 3;

    pack_w4(W1, Wp1, 8, 128, tid, 384);
    pack_w4(W2, Wp2, 8, 128, tid, 384);
    if (tid < 128){ bs[tid] = b1[tid]; bs[128 + tid] = b2[tid]; }
    __syncthreads();

    const int NSLAB = BATCHN / 16;            // 4096
    const int step  = gridDim.x * 12;

    for (int slab = blockIdx.x * 12 + w; slab < NSLAB; slab += step){
        const int row0 = slab * 16;
        uint32_t af[8][4];
        {   // A-frags straight from gmem (float2 pairs, cols ks*16+2t / +8)
            const float2* pA = (const float2*)(X + (size_t)(row0 + g) * 128);
            const float2* pB = (const float2*)(X + (size_t)(row0 + g + 8) * 128);
            #pragma unroll
            for (int ks = 0; ks < 8; ks++){
                float2 a0 = pA[ks * 8 + t],     b0v = pB[ks * 8 + t];
                float2 a2 = pA[ks * 8 + t + 4], b2v = pB[ks * 8 + t + 4];
                af[ks][0] = pack2(a0.x, a0.y);
                af[ks][1] = pack2(b0v.x, b0v.y);
                af[ks][2] = pack2(a2.x, a2.y);
                af[ks][3] = pack2(b2v.x, b2v.y);
            }
        }
        float acc[16][4];
        mma_reg<8>(af, Wp1, acc, lane);
        transition(acc, af, bs, t);
        mma_reg<8>(af, Wp2, acc, lane);
        {   // output fp16 with accurate tanh
            __half* y0 = Y + (size_t)(row0 + g) * 128;
            __half* y1 = Y + (size_t)(row0 + g + 8) * 128;
            #pragma unroll
            for (int nt = 0; nt < 16; nt++){
                int c = nt * 8 + 2 * t;
                float b0 = bs[128 + c], b1v = bs[128 + c + 1];
                *(__half2*)(y0 + c) = __floats2half2_rn(tanh_acc(acc[nt][0] + b0),
                                                        tanh_acc(acc[nt][1] + b1v));
                *(__half2*)(y1 + c) = __floats2half2_rn(tanh_acc(acc[nt][2] + b0),
                                                        tanh_acc(acc[nt][3] + b1v));
            }
        }
    }
}

// ============================================================================
// Per-group multi-head attention (8 heads x 16 dims over 8 agents) + tile x8.
// ============================================================================
__global__ void __launch_bounds__(128)
mha_kernel(const float* __restrict__ AA, const __half* __restrict__ AV,
           float* __restrict__ out)
{
    __shared__ float ks[8][128];
    __shared__ float vs[8][128];
    const int g = blockIdx.x;
    const int j = threadIdx.x;
    const size_t base = (size_t)g * 8 * 128;

    #pragma unroll
    for (int a = 0; a < 8; a++){
        ks[a][j] = AA[base + a * 128 + j];
        vs[a][j] = __half2float(AV[base + a * 128 + j]);
    }
    __syncthreads();

    float q = 0.0f;
    #pragma unroll
    for (int a = 0; a < 8; a++) q += ks[a][j];
    q *= 0.03125f;                            // mean(1/8) * rsqrt(16)

    float s[8];
    #pragma unroll
    for (int a = 0; a < 8; a++){
        float p = q * ks[a][j];
        p += __shfl_xor_sync(0xffffffff, p, 8);
        p += __shfl_xor_sync(0xffffffff, p, 4);
        p += __shfl_xor_sync(0xffffffff, p, 2);
        p += __shfl_xor_sync(0xffffffff, p, 1);
        s[a] = p;
    }
    float mx = s[0];
    #pragma unroll
    for (int a = 1; a < 8; a++) mx = fmaxf(mx, s[a]);
    float wv[8], wsum = 0.0f;
    #pragma unroll
    for (int a = 0; a < 8; a++){ wv[a] = __expf(s[a] - mx); wsum += wv[a]; }
    const float inv = 1.0f / wsum;

    float o = 0.0f;
    #pragma unroll
    for (int a = 0; a < 8; a++) o += wv[a] * vs[a][j];
    o *= inv;

    #pragma unroll
    for (int tt = 0; tt < 8; tt++)
        out[((size_t)(tt * NGRP + g)) * 128 + j] = o;
}

// ============================================================================
extern "C" void kernel_launch(void* const* d_in, const int* in_sizes, int n_in,
                              void* d_out, int out_size)
{
    const float* obs = (const float*)d_in[0];
    const float* eW1 = (const float*)d_in[1];
    const float* eb1 = (const float*)d_in[2];
    const float* eW2 = (const float*)d_in[3];
    const float* eb2 = (const float*)d_in[4];
    const float* vW1 = (const float*)d_in[5];
    const float* vb1 = (const float*)d_in[6];
    const float* vW2 = (const float*)d_in[7];
    const float* vb2 = (const float*)d_in[8];
    const float* aW1 = (const float*)d_in[9];
    const float* ab1 = (const float*)d_in[10];
    const float* aW2 = (const float*)d_in[11];
    const float* ab2 = (const float*)d_in[12];

    float* out = (float*)d_out;                 // multi_head_attention
    float* AA  = out + (size_t)BATCHN * 128;    // agent_attention

    void* pav; cudaGetSymbolAddress(&pav, g_av);
    __half* av_g = (__half*)pav;

    cudaFuncSetAttribute(fused_ev_kernel, cudaFuncAttributeMaxDynamicSharedMemorySize, F_SMEM);
    cudaFuncSetAttribute(agent_kernel,    cudaFuncAttributeMaxDynamicSharedMemorySize, A_SMEM);

    fused_ev_kernel<<<148, 384, F_SMEM>>>(obs, eW1, eb1, eW2, eb2,
                                          vW1, vb1, vW2, vb2, AA);
    agent_kernel<<<148, 384, A_SMEM>>>(AA, aW1, ab1, aW2, ab2, av_g);
    mha_kernel<<<NGRP, 128>>>(AA, av_g, out);
}